// round 10
// baseline (speedup 1.0000x reference)
#include <cuda_runtime.h>
#include <cuda_bf16.h>
#include <math.h>
#include <stdint.h>

// Problem constants
#define B      4
#define C      128
#define NSP    32768          // 32*32*32 spatial positions
#define HID    256            // heads * dim_head
#define M3     768            // 3 * HID (qkv rows)
#define HEADS  8
#define DH     32
#define QSCALE 0.17677669529663687f   // 32^-0.5
#define NSPLIT 32
#define NBLK   (NSP / 128)    // 256 n-blocks in the qkv GEMM

// -------- device scratch (static allocation; no cudaMalloc allowed) --------
__device__ float g_qkv [(size_t)B * M3 * NSP];           // k region holds exp(k); q region unused
__device__ float g_ctxp[(size_t)NSPLIT * B * HEADS * DH * DH];
__device__ float g_ksump[(size_t)B * HID * NBLK];        // exp(k) row partials per n-block
// bf16 split operands for tensor-core GEMMs
__device__ __nv_bfloat16 g_xt_hi[(size_t)B * NSP * C];
__device__ __nv_bfloat16 g_xt_lo[(size_t)B * NSP * C];
__device__ __nv_bfloat16 g_w_hi [M3 * C];
__device__ __nv_bfloat16 g_w_lo [M3 * C];
__device__ __nv_bfloat16 g_pt_hi[(size_t)B * NSP * HID]; // softmaxed q^T [b][n][c]
__device__ __nv_bfloat16 g_pt_lo[(size_t)B * NSP * HID];
__device__ __nv_bfloat16 g_M_hi [(size_t)B * C * HID];
__device__ __nv_bfloat16 g_M_lo [(size_t)B * C * HID];

// ============================================================================
// warp-MMA helpers (baseline PTX: works on compute_103 target)
// ============================================================================
__device__ __forceinline__ uint32_t smem_u32(const void* p) {
    uint32_t a;
    asm("{ .reg .u64 t; cvta.to.shared.u64 t, %1; cvt.u32.u64 %0, t; }"
        : "=r"(a) : "l"(p));
    return a;
}
__device__ __forceinline__ void ldsm4(uint32_t* r, uint32_t addr) {
    asm volatile("ldmatrix.sync.aligned.m8n8.x4.shared.b16 {%0,%1,%2,%3}, [%4];"
                 : "=r"(r[0]), "=r"(r[1]), "=r"(r[2]), "=r"(r[3]) : "r"(addr));
}
__device__ __forceinline__ void mma_bf16(float* d, const uint32_t* a,
                                         const uint32_t* b) {
    asm volatile(
        "mma.sync.aligned.m16n8k16.row.col.f32.bf16.bf16.f32 "
        "{%0,%1,%2,%3}, {%4,%5,%6,%7}, {%8,%9}, {%0,%1,%2,%3};"
        : "+f"(d[0]), "+f"(d[1]), "+f"(d[2]), "+f"(d[3])
        : "r"(a[0]), "r"(a[1]), "r"(a[2]), "r"(a[3]), "r"(b[0]), "r"(b[1]));
}

// smem layout for the mma GEMMs; row stride 136 bf16 = 272 B (pad)
#define QK_STRIDE 136
#define QK_TILE_B (128 * QK_STRIDE * 2)
#define QS_AHI 0
#define QS_ALO (QS_AHI + QK_TILE_B)
#define QS_BHI (QS_ALO + QK_TILE_B)
#define QS_BLO (QS_BHI + QK_TILE_B)
#define QS_TOTAL (QS_BLO + QK_TILE_B)       // 139264

// ============================================================================
// conversion kernels: fp32 -> (hi, lo) bf16 split
// ============================================================================
__global__ __launch_bounds__(256) void k_cvt_w(const float* __restrict__ w) {
    const int idx = blockIdx.x * 256 + threadIdx.x;
    if (idx < M3 * C) {
        float v = w[idx];
        __nv_bfloat16 h = __float2bfloat16(v);
        g_w_hi[idx] = h;
        g_w_lo[idx] = __float2bfloat16(v - __bfloat162float(h));
    }
}

// transpose x [b][c][n] fp32 -> x_t [b][n][c] bf16 hi/lo
__global__ __launch_bounds__(256) void k_cvt_x(const float* __restrict__ x) {
    __shared__ float t[32][33];
    const int bz = blockIdx.z;
    const int c0 = blockIdx.y * 32, n0 = blockIdx.x * 32;
    const int tx = threadIdx.x, ty = threadIdx.y;
    const float* xp = x + (size_t)bz * C * NSP;
#pragma unroll
    for (int j = 0; j < 4; j++)
        t[ty + 8 * j][tx] = xp[(size_t)(c0 + ty + 8 * j) * NSP + n0 + tx];
    __syncthreads();
    __nv_bfloat16* oh = g_xt_hi + (size_t)bz * NSP * C;
    __nv_bfloat16* ol = g_xt_lo + (size_t)bz * NSP * C;
#pragma unroll
    for (int j = 0; j < 4; j++) {
        const int n = n0 + ty + 8 * j, c = c0 + tx;
        float v = t[tx][ty + 8 * j];
        __nv_bfloat16 h = __float2bfloat16(v);
        oh[(size_t)n * C + c] = h;
        ol[(size_t)n * C + c] = __float2bfloat16(v - __bfloat162float(h));
    }
}

// ============================================================================
// K1 (tensor core): qkv = w_qkv @ x, bf16 hi/lo (3 chains) + fused epilogues:
//   m-blocks 0,1 (q): softmax over head dim -> p^T bf16 hi/lo (skip g_qkv)
//   m-blocks 2,3 (k): exp in place -> g_qkv; per-row partial sums -> g_ksump
//   m-blocks 4,5 (v): plain copy -> g_qkv
// grid (6, 256, B), 256 threads (8 warps, 2x4)
// ============================================================================
__global__ __launch_bounds__(256) void k_qkv_mma() {
    extern __shared__ char smem[];
    const int tid = threadIdx.x, wid = tid >> 5, lane = tid & 31;
    const int bz = blockIdx.z;
    const int mBase = blockIdx.x * 128, nBase = blockIdx.y * 128;

    {
        const __nv_bfloat16* xh = g_xt_hi + (size_t)bz * NSP * C;
        const __nv_bfloat16* xl = g_xt_lo + (size_t)bz * NSP * C;
        __nv_bfloat16* sAh = (__nv_bfloat16*)(smem + QS_AHI);
        __nv_bfloat16* sAl = (__nv_bfloat16*)(smem + QS_ALO);
        __nv_bfloat16* sBh = (__nv_bfloat16*)(smem + QS_BHI);
        __nv_bfloat16* sBl = (__nv_bfloat16*)(smem + QS_BLO);
#pragma unroll
        for (int it = 0; it < 8; it++) {
            const int idx = it * 256 + tid;
            const int row = idx >> 4, c8 = (idx & 15) << 3;
            const int so = row * QK_STRIDE + c8;
            const size_t ga = (size_t)(mBase + row) * C + c8;
            const size_t gb = (size_t)(nBase + row) * C + c8;
            *(uint4*)&sAh[so] = *(const uint4*)&g_w_hi[ga];
            *(uint4*)&sAl[so] = *(const uint4*)&g_w_lo[ga];
            *(uint4*)&sBh[so] = *(const uint4*)&xh[gb];
            *(uint4*)&sBl[so] = *(const uint4*)&xl[gb];
        }
    }
    __syncthreads();

    const uint32_t sb = smem_u32(smem);
    const int warpM = (wid >> 2) * 64;
    const int warpN = (wid & 3) * 32;

    const uint32_t aOff =
        (uint32_t)((warpM + (lane & 15)) * QK_STRIDE + ((lane >> 4) << 3)) * 2;
    const int bg = lane >> 3;
    const uint32_t bOff =
        (uint32_t)((warpN + ((bg >> 1) << 3) + (lane & 7)) * QK_STRIDE +
                   ((bg & 1) << 3)) * 2;

    float acc[4][4][4] = {};

#pragma unroll
    for (int ks = 0; ks < 8; ks++) {
        const uint32_t kOff = (uint32_t)ks * 32;
        uint32_t bh[4][2], bl[4][2];
#pragma unroll
        for (int p = 0; p < 2; p++) {
            const uint32_t po = (uint32_t)(p * 16 * QK_STRIDE * 2);
            uint32_t r[4];
            ldsm4(r, sb + QS_BHI + bOff + po + kOff);
            bh[p * 2][0] = r[0]; bh[p * 2][1] = r[1];
            bh[p * 2 + 1][0] = r[2]; bh[p * 2 + 1][1] = r[3];
            ldsm4(r, sb + QS_BLO + bOff + po + kOff);
            bl[p * 2][0] = r[0]; bl[p * 2][1] = r[1];
            bl[p * 2 + 1][0] = r[2]; bl[p * 2 + 1][1] = r[3];
        }
#pragma unroll
        for (int mi = 0; mi < 4; mi++) {
            const uint32_t mo = (uint32_t)(mi * 16 * QK_STRIDE * 2);
            uint32_t ah[4], al[4];
            ldsm4(ah, sb + QS_AHI + aOff + mo + kOff);
            ldsm4(al, sb + QS_ALO + aOff + mo + kOff);
#pragma unroll
            for (int ni = 0; ni < 4; ni++) {
                mma_bf16(acc[mi][ni], ah, bh[ni]);
                mma_bf16(acc[mi][ni], ah, bl[ni]);
                mma_bf16(acc[mi][ni], al, bh[ni]);
            }
        }
    }

    // ---- stage accumulators to smem ----
    __syncthreads();
    float* stage = (float*)smem;           // [128][132]
#pragma unroll
    for (int mi = 0; mi < 4; mi++) {
        const int r0 = warpM + mi * 16 + (lane >> 2);
#pragma unroll
        for (int ni = 0; ni < 4; ni++) {
            const int c0 = warpN + ni * 8 + (lane & 3) * 2;
            stage[r0 * 132 + c0]           = acc[mi][ni][0];
            stage[r0 * 132 + c0 + 1]       = acc[mi][ni][1];
            stage[(r0 + 8) * 132 + c0]     = acc[mi][ni][2];
            stage[(r0 + 8) * 132 + c0 + 1] = acc[mi][ni][3];
        }
    }
    __syncthreads();

    if (blockIdx.x < 2) {
        // ---- q path: softmax over each 32-row head group, write p^T bf16 ----
        const int col = tid & 127, half = tid >> 7;   // 2 head-groups per thread
        __nv_bfloat16* ph = g_pt_hi + (size_t)bz * NSP * HID;
        __nv_bfloat16* pl = g_pt_lo + (size_t)bz * NSP * HID;
#pragma unroll
        for (int hg = 0; hg < 2; hg++) {
            const int r0 = half * 64 + hg * 32;
            float e[DH];
            float s = 0.f;
#pragma unroll
            for (int j = 0; j < DH; j++) {
                e[j] = __expf(stage[(r0 + j) * 132 + col]);
                s += e[j];
            }
            const float inv = QSCALE / s;
            const size_t base = (size_t)(nBase + col) * HID + mBase + r0;
#pragma unroll
            for (int j = 0; j < DH; j += 2) {
                __nv_bfloat162 h2, l2;
                float p0 = e[j] * inv, p1 = e[j + 1] * inv;
                h2.x = __float2bfloat16(p0);
                h2.y = __float2bfloat16(p1);
                l2.x = __float2bfloat16(p0 - __bfloat162float(h2.x));
                l2.y = __float2bfloat16(p1 - __bfloat162float(h2.y));
                *(__nv_bfloat162*)&ph[base + j] = h2;
                *(__nv_bfloat162*)&pl[base + j] = l2;
            }
        }
        return;                                       // q never hits g_qkv
    }

    if (blockIdx.x < 4) {
        // ---- k path: exp in place + per-row partial sums ----
        const int r = tid >> 1, chalf = (tid & 1) * 64;
        float s = 0.f;
#pragma unroll
        for (int c = 0; c < 64; c++) {
            float e = __expf(stage[r * 132 + chalf + c]);
            stage[r * 132 + chalf + c] = e;
            s += e;
        }
        s += __shfl_xor_sync(0xFFFFFFFFu, s, 1);
        if ((tid & 1) == 0) {
            const int kr = (mBase - 256) + r;         // global k row 0..255
            g_ksump[((size_t)bz * HID + kr) * NBLK + blockIdx.y] = s;
        }
        __syncthreads();
    }

    // ---- k (exp'd) and v: copy stage -> g_qkv ----
    float* Cp = g_qkv + ((size_t)bz * M3 + mBase) * NSP + nBase;
#pragma unroll
    for (int it = 0; it < 16; it++) {
        const int idx = it * 256 + tid;
        const int row = idx >> 5, c4 = (idx & 31) << 2;
        *(float4*)&Cp[(size_t)row * NSP + c4] = *(float4*)&stage[row * 132 + c4];
    }
}

// ============================================================================
// K2: context partials: ctx[b,h,d,e] += sum_n ek[d,n] * v[e,n]
// (ek = exp(k) precomputed). grid (NSPLIT, HEADS, B), 64 threads, 4x4/thread.
// ============================================================================
__global__ __launch_bounds__(64) void k_ctx() {
    const int sp = blockIdx.x, h = blockIdx.y, b = blockIdx.z;
    const float* ekp = g_qkv + ((size_t)b * M3 + HID     + h * DH) * NSP;
    const float* vp  = g_qkv + ((size_t)b * M3 + 2 * HID + h * DH) * NSP;

    __shared__ float ks[32][132];
    __shared__ float vs[32][132];

    const int tid = threadIdx.x;
    const int d0 = (tid >> 3) << 2;   // 0,4,..,28
    const int e0 = (tid & 7) << 2;    // 0,4,..,28
    float acc[4][4] = {};
    const int nb = sp * 1024;

    for (int t = 0; t < 8; t++) {
        const int n0 = nb + t * 128;
#pragma unroll
        for (int i = 0; i < 16; i++) {
            const int idx = i * 64 + tid;              // 1024 float4 per array
            const int row = idx >> 5, c4 = (idx & 31) << 2;
            *(float4*)&ks[row][c4] = *(const float4*)&ekp[(size_t)row * NSP + n0 + c4];
            *(float4*)&vs[row][c4] = *(const float4*)&vp [(size_t)row * NSP + n0 + c4];
        }
        __syncthreads();
#pragma unroll
        for (int j = 0; j < 128; j += 4) {
            float4 ka[4], va[4];
#pragma unroll
            for (int i = 0; i < 4; i++) {
                ka[i] = *(const float4*)&ks[d0 + i][j];
                va[i] = *(const float4*)&vs[e0 + i][j];
            }
#pragma unroll
            for (int a = 0; a < 4; a++)
#pragma unroll
                for (int c = 0; c < 4; c++)
                    acc[a][c] = fmaf(ka[a].x, va[c].x,
                               fmaf(ka[a].y, va[c].y,
                               fmaf(ka[a].z, va[c].z,
                               fmaf(ka[a].w, va[c].w, acc[a][c]))));
        }
        __syncthreads();
    }
    float* cp = &g_ctxp[(((size_t)sp * B + b) * HEADS + h) * (DH * DH)];
#pragma unroll
    for (int a = 0; a < 4; a++)
#pragma unroll
        for (int c = 0; c < 4; c++)
            cp[(d0 + a) * 32 + e0 + c] = acc[a][c];
}

// ============================================================================
// K3: reduce ctx & ksum partials, normalize, fold with w_out -> bf16 hi/lo
// grid B, 256 threads
// ============================================================================
__global__ __launch_bounds__(256) void k_fold(const float* __restrict__ wout) {
    const int b = blockIdx.x;
    __shared__ float ctx[HEADS * DH * DH];
    __shared__ float ks_s[HID];
    const int tid = threadIdx.x;

    {
        const float* kp = &g_ksump[((size_t)b * HID + tid) * NBLK];
        float s = 0.f;
        for (int nb = 0; nb < NBLK; nb += 4) {
            float4 v = *(const float4*)&kp[nb];
            s += v.x + v.y + v.z + v.w;
        }
        ks_s[tid] = s;
    }
    __syncthreads();

    for (int idx = tid; idx < HEADS * DH * DH; idx += 256) {
        float s = 0.f;
        for (int sp = 0; sp < NSPLIT; sp++)
            s += g_ctxp[(((size_t)sp * B + b) * HEADS) * (DH * DH) + idx];
        const int h = idx >> 10, de = idx & 1023, d = de >> 5;
        ctx[idx] = s / ks_s[h * DH + d];
    }
    __syncthreads();

    for (int idx = tid; idx < C * HID; idx += 256) {
        const int o = idx >> 8, cc = idx & 255;
        const int h = cc >> 5, d = cc & 31;
        const float* wrow = &wout[o * HID + h * DH];
        const float* crow = &ctx[h * (DH * DH) + d * 32];
        float s = 0.f;
#pragma unroll
        for (int e = 0; e < DH; e++) s = fmaf(wrow[e], crow[e], s);
        __nv_bfloat16 hh = __float2bfloat16(s);
        g_M_hi[(size_t)b * C * HID + idx] = hh;
        g_M_lo[(size_t)b * C * HID + idx] =
            __float2bfloat16(s - __bfloat162float(hh));
    }
}

// ============================================================================
// K4 (tensor core): out[b][o][n] = sum_c M[o][c] * p[c][n] + bias[o]
// grid (NSP/128, B), 256 threads; K=256 as two resident halves.
// ============================================================================
__global__ __launch_bounds__(256) void k_out_mma(float* __restrict__ out,
                                                const float* __restrict__ bout) {
    extern __shared__ char smem[];
    const int tid = threadIdx.x, wid = tid >> 5, lane = tid & 31;
    const int bz = blockIdx.y;
    const int nBase = blockIdx.x * 128;

    const uint32_t sb = smem_u32(smem);
    const int warpM = (wid >> 2) * 64;
    const int warpN = (wid & 3) * 32;
    const uint32_t aOff =
        (uint32_t)((warpM + (lane & 15)) * QK_STRIDE + ((lane >> 4) << 3)) * 2;
    const int bg = lane >> 3;
    const uint32_t bOff =
        (uint32_t)((warpN + ((bg >> 1) << 3) + (lane & 7)) * QK_STRIDE +
                   ((bg & 1) << 3)) * 2;

    float acc[4][4][4] = {};

    for (int kh = 0; kh < 2; kh++) {
        if (kh) __syncthreads();
        {
            const __nv_bfloat16* mh = g_M_hi + (size_t)bz * C * HID + kh * 128;
            const __nv_bfloat16* ml = g_M_lo + (size_t)bz * C * HID + kh * 128;
            const __nv_bfloat16* ph = g_pt_hi + (size_t)bz * NSP * HID + kh * 128;
            const __nv_bfloat16* pl = g_pt_lo + (size_t)bz * NSP * HID + kh * 128;
            __nv_bfloat16* sAh = (__nv_bfloat16*)(smem + QS_AHI);
            __nv_bfloat16* sAl = (__nv_bfloat16*)(smem + QS_ALO);
            __nv_bfloat16* sBh = (__nv_bfloat16*)(smem + QS_BHI);
            __nv_bfloat16* sBl = (__nv_bfloat16*)(smem + QS_BLO);
#pragma unroll
            for (int it = 0; it < 8; it++) {
                const int idx = it * 256 + tid;
                const int row = idx >> 4, c8 = (idx & 15) << 3;
                const int so = row * QK_STRIDE + c8;
                const size_t ga = (size_t)row * HID + c8;
                const size_t gb = (size_t)(nBase + row) * HID + c8;
                *(uint4*)&sAh[so] = *(const uint4*)&mh[ga];
                *(uint4*)&sAl[so] = *(const uint4*)&ml[ga];
                *(uint4*)&sBh[so] = *(const uint4*)&ph[gb];
                *(uint4*)&sBl[so] = *(const uint4*)&pl[gb];
            }
        }
        __syncthreads();

#pragma unroll
        for (int ks = 0; ks < 8; ks++) {
            const uint32_t kOff = (uint32_t)ks * 32;
            uint32_t bh[4][2], bl[4][2];
#pragma unroll
            for (int p = 0; p < 2; p++) {
                const uint32_t po = (uint32_t)(p * 16 * QK_STRIDE * 2);
                uint32_t r[4];
                ldsm4(r, sb + QS_BHI + bOff + po + kOff);
                bh[p * 2][0] = r[0]; bh[p * 2][1] = r[1];
                bh[p * 2 + 1][0] = r[2]; bh[p * 2 + 1][1] = r[3];
                ldsm4(r, sb + QS_BLO + bOff + po + kOff);
                bl[p * 2][0] = r[0]; bl[p * 2][1] = r[1];
                bl[p * 2 + 1][0] = r[2]; bl[p * 2 + 1][1] = r[3];
            }
#pragma unroll
            for (int mi = 0; mi < 4; mi++) {
                const uint32_t mo = (uint32_t)(mi * 16 * QK_STRIDE * 2);
                uint32_t ah[4], al[4];
                ldsm4(ah, sb + QS_AHI + aOff + mo + kOff);
                ldsm4(al, sb + QS_ALO + aOff + mo + kOff);
#pragma unroll
                for (int ni = 0; ni < 4; ni++) {
                    mma_bf16(acc[mi][ni], ah, bh[ni]);
                    mma_bf16(acc[mi][ni], ah, bl[ni]);
                    mma_bf16(acc[mi][ni], al, bh[ni]);
                }
            }
        }
    }

    __syncthreads();
    float* stage = (float*)smem;           // [128][132]
#pragma unroll
    for (int mi = 0; mi < 4; mi++) {
        const int r0 = warpM + mi * 16 + (lane >> 2);
#pragma unroll
        for (int ni = 0; ni < 4; ni++) {
            const int c0 = warpN + ni * 8 + (lane & 3) * 2;
            stage[r0 * 132 + c0]           = acc[mi][ni][0];
            stage[r0 * 132 + c0 + 1]       = acc[mi][ni][1];
            stage[(r0 + 8) * 132 + c0]     = acc[mi][ni][2];
            stage[(r0 + 8) * 132 + c0 + 1] = acc[mi][ni][3];
        }
    }
    __syncthreads();
    float* Cp = out + (size_t)bz * C * NSP + nBase;
#pragma unroll
    for (int it = 0; it < 16; it++) {
        const int idx = it * 256 + tid;
        const int row = idx >> 5, c4 = (idx & 31) << 2;
        const float bb = __ldg(&bout[row]);
        float4 v = *(float4*)&stage[row * 132 + c4];
        v.x += bb; v.y += bb; v.z += bb; v.w += bb;
        *(float4*)&Cp[(size_t)row * NSP + c4] = v;
    }
}

// ============================================================================
extern "C" void kernel_launch(void* const* d_in, const int* in_sizes, int n_in,
                              void* d_out, int out_size) {
    const float* x    = (const float*)d_in[0];
    const float* wqkv = (const float*)d_in[1];
    const float* wout = (const float*)d_in[2];
    const float* bout = (const float*)d_in[3];
    float* out = (float*)d_out;

    cudaFuncSetAttribute(k_qkv_mma, cudaFuncAttributeMaxDynamicSharedMemorySize,
                         QS_TOTAL);
    cudaFuncSetAttribute(k_out_mma, cudaFuncAttributeMaxDynamicSharedMemorySize,
                         QS_TOTAL);

    k_cvt_w  <<<(M3 * C + 255) / 256, 256>>>(wqkv);
    k_cvt_x  <<<dim3(NSP / 32, C / 32, B), dim3(32, 8)>>>(x);
    k_qkv_mma<<<dim3(M3 / 128, NBLK, B), 256, QS_TOTAL>>>();
    k_ctx    <<<dim3(NSPLIT, HEADS, B), 64>>>();
    k_fold   <<<B, 256>>>(wout);
    k_out_mma<<<dim3(NSP / 128, B), 256, QS_TOTAL>>>(out, bout);
}

// round 12
// speedup vs baseline: 1.1053x; 1.1053x over previous
#include <cuda_runtime.h>
#include <cuda_bf16.h>
#include <math.h>
#include <stdint.h>

// Problem constants
#define B      4
#define C      128
#define NSP    32768          // 32*32*32 spatial positions
#define HID    256            // heads * dim_head
#define M3     768            // 3 * HID (qkv rows)
#define HEADS  8
#define DH     32
#define QSCALE 0.17677669529663687f   // 32^-0.5
#define NSPLIT 32
#define NBLK   (NSP / 128)    // 256 n-blocks in the qkv GEMM
#define CTXG   4              // column-split groups in k_ctx

// -------- device scratch (static allocation; no cudaMalloc allowed) --------
__device__ float g_qkv [(size_t)B * M3 * NSP];           // k region holds exp(k); q region unused
__device__ float g_ctxp[(size_t)NSPLIT * CTXG * B * HEADS * DH * DH];
__device__ float g_ksump[(size_t)B * HID * NBLK];        // exp(k) row partials per n-block
// bf16 split operands for tensor-core GEMMs
__device__ __nv_bfloat16 g_xt_hi[(size_t)B * NSP * C];
__device__ __nv_bfloat16 g_xt_lo[(size_t)B * NSP * C];
__device__ __nv_bfloat16 g_w_hi [M3 * C];
__device__ __nv_bfloat16 g_w_lo [M3 * C];
__device__ __nv_bfloat16 g_pt_hi[(size_t)B * NSP * HID]; // softmaxed q^T [b][n][c]
__device__ __nv_bfloat16 g_pt_lo[(size_t)B * NSP * HID];
__device__ __nv_bfloat16 g_M_hi [(size_t)B * C * HID];
__device__ __nv_bfloat16 g_M_lo [(size_t)B * C * HID];

// ============================================================================
// warp-MMA helpers (baseline PTX: works on compute_103 target)
// ============================================================================
__device__ __forceinline__ uint32_t smem_u32(const void* p) {
    uint32_t a;
    asm("{ .reg .u64 t; cvta.to.shared.u64 t, %1; cvt.u32.u64 %0, t; }"
        : "=r"(a) : "l"(p));
    return a;
}
__device__ __forceinline__ void ldsm4(uint32_t* r, uint32_t addr) {
    asm volatile("ldmatrix.sync.aligned.m8n8.x4.shared.b16 {%0,%1,%2,%3}, [%4];"
                 : "=r"(r[0]), "=r"(r[1]), "=r"(r[2]), "=r"(r[3]) : "r"(addr));
}
__device__ __forceinline__ void mma_bf16(float* d, const uint32_t* a,
                                         const uint32_t* b) {
    asm volatile(
        "mma.sync.aligned.m16n8k16.row.col.f32.bf16.bf16.f32 "
        "{%0,%1,%2,%3}, {%4,%5,%6,%7}, {%8,%9}, {%0,%1,%2,%3};"
        : "+f"(d[0]), "+f"(d[1]), "+f"(d[2]), "+f"(d[3])
        : "r"(a[0]), "r"(a[1]), "r"(a[2]), "r"(a[3]), "r"(b[0]), "r"(b[1]));
}

// smem layout for the mma GEMMs; row stride 136 bf16 = 272 B (pad)
#define QK_STRIDE 136
#define QK_TILE_B (128 * QK_STRIDE * 2)
#define QS_AHI 0
#define QS_ALO (QS_AHI + QK_TILE_B)
#define QS_BHI (QS_ALO + QK_TILE_B)
#define QS_BLO (QS_BHI + QK_TILE_B)
#define QS_TOTAL (QS_BLO + QK_TILE_B)       // 139264

// ============================================================================
// conversion kernels: fp32 -> (hi, lo) bf16 split
// ============================================================================
__global__ __launch_bounds__(256) void k_cvt_w(const float* __restrict__ w) {
    const int idx = blockIdx.x * 256 + threadIdx.x;
    if (idx < M3 * C) {
        float v = w[idx];
        __nv_bfloat16 h = __float2bfloat16(v);
        g_w_hi[idx] = h;
        g_w_lo[idx] = __float2bfloat16(v - __bfloat162float(h));
    }
}

// transpose x [b][c][n] fp32 -> x_t [b][n][c] bf16 hi/lo
__global__ __launch_bounds__(256) void k_cvt_x(const float* __restrict__ x) {
    __shared__ float t[32][33];
    const int bz = blockIdx.z;
    const int c0 = blockIdx.y * 32, n0 = blockIdx.x * 32;
    const int tx = threadIdx.x, ty = threadIdx.y;
    const float* xp = x + (size_t)bz * C * NSP;
#pragma unroll
    for (int j = 0; j < 4; j++)
        t[ty + 8 * j][tx] = xp[(size_t)(c0 + ty + 8 * j) * NSP + n0 + tx];
    __syncthreads();
    __nv_bfloat16* oh = g_xt_hi + (size_t)bz * NSP * C;
    __nv_bfloat16* ol = g_xt_lo + (size_t)bz * NSP * C;
#pragma unroll
    for (int j = 0; j < 4; j++) {
        const int n = n0 + ty + 8 * j, c = c0 + tx;
        float v = t[tx][ty + 8 * j];
        __nv_bfloat16 h = __float2bfloat16(v);
        oh[(size_t)n * C + c] = h;
        ol[(size_t)n * C + c] = __float2bfloat16(v - __bfloat162float(h));
    }
}

// ============================================================================
// K1 (tensor core): qkv = w_qkv @ x, bf16 hi/lo (3 chains) + fused epilogues:
//   m-blocks 0,1 (q): TRANSPOSED stage -> softmax along contiguous c ->
//                     coalesced p^T bf16 hi/lo writes (skip g_qkv)
//   m-blocks 2,3 (k): exp in place -> g_qkv; per-row partial sums -> g_ksump
//   m-blocks 4,5 (v): plain copy -> g_qkv
// grid (6, 256, B), 256 threads (8 warps, 2x4)
// ============================================================================
__global__ __launch_bounds__(256) void k_qkv_mma() {
    extern __shared__ char smem[];
    const int tid = threadIdx.x, wid = tid >> 5, lane = tid & 31;
    const int bz = blockIdx.z;
    const int mBase = blockIdx.x * 128, nBase = blockIdx.y * 128;

    {
        const __nv_bfloat16* xh = g_xt_hi + (size_t)bz * NSP * C;
        const __nv_bfloat16* xl = g_xt_lo + (size_t)bz * NSP * C;
        __nv_bfloat16* sAh = (__nv_bfloat16*)(smem + QS_AHI);
        __nv_bfloat16* sAl = (__nv_bfloat16*)(smem + QS_ALO);
        __nv_bfloat16* sBh = (__nv_bfloat16*)(smem + QS_BHI);
        __nv_bfloat16* sBl = (__nv_bfloat16*)(smem + QS_BLO);
#pragma unroll
        for (int it = 0; it < 8; it++) {
            const int idx = it * 256 + tid;
            const int row = idx >> 4, c8 = (idx & 15) << 3;
            const int so = row * QK_STRIDE + c8;
            const size_t ga = (size_t)(mBase + row) * C + c8;
            const size_t gb = (size_t)(nBase + row) * C + c8;
            *(uint4*)&sAh[so] = *(const uint4*)&g_w_hi[ga];
            *(uint4*)&sAl[so] = *(const uint4*)&g_w_lo[ga];
            *(uint4*)&sBh[so] = *(const uint4*)&xh[gb];
            *(uint4*)&sBl[so] = *(const uint4*)&xl[gb];
        }
    }
    __syncthreads();

    const uint32_t sb = smem_u32(smem);
    const int warpM = (wid >> 2) * 64;
    const int warpN = (wid & 3) * 32;

    const uint32_t aOff =
        (uint32_t)((warpM + (lane & 15)) * QK_STRIDE + ((lane >> 4) << 3)) * 2;
    const int bg = lane >> 3;
    const uint32_t bOff =
        (uint32_t)((warpN + ((bg >> 1) << 3) + (lane & 7)) * QK_STRIDE +
                   ((bg & 1) << 3)) * 2;

    float acc[4][4][4] = {};

#pragma unroll
    for (int ks = 0; ks < 8; ks++) {
        const uint32_t kOff = (uint32_t)ks * 32;
        uint32_t bh[4][2], bl[4][2];
#pragma unroll
        for (int p = 0; p < 2; p++) {
            const uint32_t po = (uint32_t)(p * 16 * QK_STRIDE * 2);
            uint32_t r[4];
            ldsm4(r, sb + QS_BHI + bOff + po + kOff);
            bh[p * 2][0] = r[0]; bh[p * 2][1] = r[1];
            bh[p * 2 + 1][0] = r[2]; bh[p * 2 + 1][1] = r[3];
            ldsm4(r, sb + QS_BLO + bOff + po + kOff);
            bl[p * 2][0] = r[0]; bl[p * 2][1] = r[1];
            bl[p * 2 + 1][0] = r[2]; bl[p * 2 + 1][1] = r[3];
        }
#pragma unroll
        for (int mi = 0; mi < 4; mi++) {
            const uint32_t mo = (uint32_t)(mi * 16 * QK_STRIDE * 2);
            uint32_t ah[4], al[4];
            ldsm4(ah, sb + QS_AHI + aOff + mo + kOff);
            ldsm4(al, sb + QS_ALO + aOff + mo + kOff);
#pragma unroll
            for (int ni = 0; ni < 4; ni++) {
                mma_bf16(acc[mi][ni], ah, bh[ni]);
                mma_bf16(acc[mi][ni], ah, bl[ni]);
                mma_bf16(acc[mi][ni], al, bh[ni]);
            }
        }
    }

    __syncthreads();
    float* stage = (float*)smem;           // [128][132]

    if (blockIdx.x < 2) {
        // ---- q path: store TRANSPOSED stage[n][c]  (value (r,c)->stage[c*132+r])
#pragma unroll
        for (int mi = 0; mi < 4; mi++) {
            const int r0 = warpM + mi * 16 + (lane >> 2);
#pragma unroll
            for (int ni = 0; ni < 4; ni++) {
                const int c0 = warpN + ni * 8 + (lane & 3) * 2;
                stage[c0 * 132 + r0]             = acc[mi][ni][0];
                stage[(c0 + 1) * 132 + r0]       = acc[mi][ni][1];
                stage[c0 * 132 + r0 + 8]         = acc[mi][ni][2];
                stage[(c0 + 1) * 132 + r0 + 8]   = acc[mi][ni][3];
            }
        }
        __syncthreads();

        // softmax per (n, head): thread -> n = tid>>1, heads {2*(tid&1), 2*(tid&1)+1}
        {
            const int n = tid >> 1;
            float* row = &stage[n * 132];
#pragma unroll
            for (int hh = 0; hh < 2; hh++) {
                const int hg = (tid & 1) * 2 + hh;
                float e[DH];
                float s = 0.f;
#pragma unroll
                for (int j = 0; j < DH; j += 4) {
                    float4 v = *(const float4*)&row[hg * DH + j];
                    e[j] = __expf(v.x); e[j + 1] = __expf(v.y);
                    e[j + 2] = __expf(v.z); e[j + 3] = __expf(v.w);
                    s += e[j] + e[j + 1] + e[j + 2] + e[j + 3];
                }
                const float inv = QSCALE / s;
#pragma unroll
                for (int j = 0; j < DH; j += 4)
                    *(float4*)&row[hg * DH + j] = make_float4(
                        e[j] * inv, e[j + 1] * inv, e[j + 2] * inv, e[j + 3] * inv);
            }
        }
        __syncthreads();

        // coalesced writes: lanes sweep consecutive c at fixed n
        __nv_bfloat16* ph = g_pt_hi + (size_t)bz * NSP * HID;
        __nv_bfloat16* pl = g_pt_lo + (size_t)bz * NSP * HID;
#pragma unroll
        for (int it = 0; it < 32; it++) {
            const int linear = it * 256 + tid;
            const int n = linear >> 6, c = (linear & 63) * 2;
            const float p0 = stage[n * 132 + c];
            const float p1 = stage[n * 132 + c + 1];
            __nv_bfloat162 h2, l2;
            h2.x = __float2bfloat16(p0);
            h2.y = __float2bfloat16(p1);
            l2.x = __float2bfloat16(p0 - __bfloat162float(h2.x));
            l2.y = __float2bfloat16(p1 - __bfloat162float(h2.y));
            const size_t o = (size_t)(nBase + n) * HID + mBase + c;
            *(__nv_bfloat162*)&ph[o] = h2;
            *(__nv_bfloat162*)&pl[o] = l2;
        }
        return;                                       // q never hits g_qkv
    }

    // ---- k / v: normal stage layout ----
#pragma unroll
    for (int mi = 0; mi < 4; mi++) {
        const int r0 = warpM + mi * 16 + (lane >> 2);
#pragma unroll
        for (int ni = 0; ni < 4; ni++) {
            const int c0 = warpN + ni * 8 + (lane & 3) * 2;
            stage[r0 * 132 + c0]           = acc[mi][ni][0];
            stage[r0 * 132 + c0 + 1]       = acc[mi][ni][1];
            stage[(r0 + 8) * 132 + c0]     = acc[mi][ni][2];
            stage[(r0 + 8) * 132 + c0 + 1] = acc[mi][ni][3];
        }
    }
    __syncthreads();

    if (blockIdx.x < 4) {
        // k path: exp in place + per-row partial sums
        const int r = tid >> 1, chalf = (tid & 1) * 64;
        float s = 0.f;
#pragma unroll
        for (int c = 0; c < 64; c++) {
            float e = __expf(stage[r * 132 + chalf + c]);
            stage[r * 132 + chalf + c] = e;
            s += e;
        }
        s += __shfl_xor_sync(0xFFFFFFFFu, s, 1);
        if ((tid & 1) == 0) {
            const int kr = (mBase - 256) + r;         // global k row 0..255
            g_ksump[((size_t)bz * HID + kr) * NBLK + blockIdx.y] = s;
        }
        __syncthreads();
    }

    float* Cp = g_qkv + ((size_t)bz * M3 + mBase) * NSP + nBase;
#pragma unroll
    for (int it = 0; it < 16; it++) {
        const int idx = it * 256 + tid;
        const int row = idx >> 5, c4 = (idx & 31) << 2;
        *(float4*)&Cp[(size_t)row * NSP + c4] = *(float4*)&stage[row * 132 + c4];
    }
}

// ============================================================================
// K2: context partials: ctx[b,h,d,e] += sum_n ek[d,n] * v[e,n]
// 256 threads = 4 groups x 64; group g covers columns [g*32, g*32+32),
// 4x4 outputs per thread; per-group partials -> g_ctxp (CTXG-widened).
// grid (NSPLIT, HEADS, B)
// ============================================================================
__global__ __launch_bounds__(256) void k_ctx() {
    const int sp = blockIdx.x, h = blockIdx.y, b = blockIdx.z;
    const float* ekp = g_qkv + ((size_t)b * M3 + HID     + h * DH) * NSP;
    const float* vp  = g_qkv + ((size_t)b * M3 + 2 * HID + h * DH) * NSP;

    __shared__ float ks[32][132];
    __shared__ float vs[32][132];

    const int tid = threadIdx.x;
    const int g = tid >> 6, t = tid & 63;
    const int d0 = (t >> 3) << 2;     // 0,4,..,28
    const int e0 = (t & 7) << 2;      // 0,4,..,28
    const int jbase = g * 32;
    float acc[4][4] = {};
    const int nb = sp * 1024;

    for (int tt = 0; tt < 8; tt++) {
        const int n0 = nb + tt * 128;
#pragma unroll
        for (int i = 0; i < 4; i++) {
            const int idx = i * 256 + tid;             // 1024 float4 per array
            const int row = idx >> 5, c4 = (idx & 31) << 2;
            *(float4*)&ks[row][c4] = *(const float4*)&ekp[(size_t)row * NSP + n0 + c4];
            *(float4*)&vs[row][c4] = *(const float4*)&vp [(size_t)row * NSP + n0 + c4];
        }
        __syncthreads();
#pragma unroll
        for (int j = jbase; j < jbase + 32; j += 4) {
            float4 ka[4], va[4];
#pragma unroll
            for (int i = 0; i < 4; i++) {
                ka[i] = *(const float4*)&ks[d0 + i][j];
                va[i] = *(const float4*)&vs[e0 + i][j];
            }
#pragma unroll
            for (int a = 0; a < 4; a++)
#pragma unroll
                for (int c = 0; c < 4; c++)
                    acc[a][c] = fmaf(ka[a].x, va[c].x,
                               fmaf(ka[a].y, va[c].y,
                               fmaf(ka[a].z, va[c].z,
                               fmaf(ka[a].w, va[c].w, acc[a][c]))));
        }
        __syncthreads();
    }
    float* cp = &g_ctxp[((((size_t)sp * CTXG + g) * B + b) * HEADS + h) * (DH * DH)];
#pragma unroll
    for (int a = 0; a < 4; a++)
#pragma unroll
        for (int c = 0; c < 4; c++)
            cp[(d0 + a) * 32 + e0 + c] = acc[a][c];
}

// ============================================================================
// K3: reduce ctx & ksum partials, normalize, fold with w_out -> bf16 hi/lo
// grid B, 256 threads
// ============================================================================
__global__ __launch_bounds__(256) void k_fold(const float* __restrict__ wout) {
    const int b = blockIdx.x;
    __shared__ float ctx[HEADS * DH * DH];
    __shared__ float ks_s[HID];
    const int tid = threadIdx.x;

    {
        const float* kp = &g_ksump[((size_t)b * HID + tid) * NBLK];
        float s = 0.f;
        for (int nb = 0; nb < NBLK; nb += 4) {
            float4 v = *(const float4*)&kp[nb];
            s += v.x + v.y + v.z + v.w;
        }
        ks_s[tid] = s;
    }
    __syncthreads();

    for (int idx = tid; idx < HEADS * DH * DH; idx += 256) {
        float s = 0.f;
        for (int sp = 0; sp < NSPLIT * CTXG; sp++)
            s += g_ctxp[(((size_t)sp * B + b) * HEADS) * (DH * DH) + idx];
        const int h = idx >> 10, de = idx & 1023, d = de >> 5;
        ctx[idx] = s / ks_s[h * DH + d];
    }
    __syncthreads();

    for (int idx = tid; idx < C * HID; idx += 256) {
        const int o = idx >> 8, cc = idx & 255;
        const int h = cc >> 5, d = cc & 31;
        const float* wrow = &wout[o * HID + h * DH];
        const float* crow = &ctx[h * (DH * DH) + d * 32];
        float s = 0.f;
#pragma unroll
        for (int e = 0; e < DH; e++) s = fmaf(wrow[e], crow[e], s);
        __nv_bfloat16 hh = __float2bfloat16(s);
        g_M_hi[(size_t)b * C * HID + idx] = hh;
        g_M_lo[(size_t)b * C * HID + idx] =
            __float2bfloat16(s - __bfloat162float(hh));
    }
}

// ============================================================================
// K4 (tensor core): out[b][o][n] = sum_c M[o][c] * p[c][n] + bias[o]
// grid (NSP/128, B), 256 threads; K=256 as two resident halves.
// ============================================================================
__global__ __launch_bounds__(256) void k_out_mma(float* __restrict__ out,
                                                const float* __restrict__ bout) {
    extern __shared__ char smem[];
    const int tid = threadIdx.x, wid = tid >> 5, lane = tid & 31;
    const int bz = blockIdx.y;
    const int nBase = blockIdx.x * 128;

    const uint32_t sb = smem_u32(smem);
    const int warpM = (wid >> 2) * 64;
    const int warpN = (wid & 3) * 32;
    const uint32_t aOff =
        (uint32_t)((warpM + (lane & 15)) * QK_STRIDE + ((lane >> 4) << 3)) * 2;
    const int bg = lane >> 3;
    const uint32_t bOff =
        (uint32_t)((warpN + ((bg >> 1) << 3) + (lane & 7)) * QK_STRIDE +
                   ((bg & 1) << 3)) * 2;

    float acc[4][4][4] = {};

    for (int kh = 0; kh < 2; kh++) {
        if (kh) __syncthreads();
        {
            const __nv_bfloat16* mh = g_M_hi + (size_t)bz * C * HID + kh * 128;
            const __nv_bfloat16* ml = g_M_lo + (size_t)bz * C * HID + kh * 128;
            const __nv_bfloat16* ph = g_pt_hi + (size_t)bz * NSP * HID + kh * 128;
            const __nv_bfloat16* pl = g_pt_lo + (size_t)bz * NSP * HID + kh * 128;
            __nv_bfloat16* sAh = (__nv_bfloat16*)(smem + QS_AHI);
            __nv_bfloat16* sAl = (__nv_bfloat16*)(smem + QS_ALO);
            __nv_bfloat16* sBh = (__nv_bfloat16*)(smem + QS_BHI);
            __nv_bfloat16* sBl = (__nv_bfloat16*)(smem + QS_BLO);
#pragma unroll
            for (int it = 0; it < 8; it++) {
                const int idx = it * 256 + tid;
                const int row = idx >> 4, c8 = (idx & 15) << 3;
                const int so = row * QK_STRIDE + c8;
                const size_t ga = (size_t)row * HID + c8;
                const size_t gb = (size_t)(nBase + row) * HID + c8;
                *(uint4*)&sAh[so] = *(const uint4*)&mh[ga];
                *(uint4*)&sAl[so] = *(const uint4*)&ml[ga];
                *(uint4*)&sBh[so] = *(const uint4*)&ph[gb];
                *(uint4*)&sBl[so] = *(const uint4*)&pl[gb];
            }
        }
        __syncthreads();

#pragma unroll
        for (int ks = 0; ks < 8; ks++) {
            const uint32_t kOff = (uint32_t)ks * 32;
            uint32_t bh[4][2], bl[4][2];
#pragma unroll
            for (int p = 0; p < 2; p++) {
                const uint32_t po = (uint32_t)(p * 16 * QK_STRIDE * 2);
                uint32_t r[4];
                ldsm4(r, sb + QS_BHI + bOff + po + kOff);
                bh[p * 2][0] = r[0]; bh[p * 2][1] = r[1];
                bh[p * 2 + 1][0] = r[2]; bh[p * 2 + 1][1] = r[3];
                ldsm4(r, sb + QS_BLO + bOff + po + kOff);
                bl[p * 2][0] = r[0]; bl[p * 2][1] = r[1];
                bl[p * 2 + 1][0] = r[2]; bl[p * 2 + 1][1] = r[3];
            }
#pragma unroll
            for (int mi = 0; mi < 4; mi++) {
                const uint32_t mo = (uint32_t)(mi * 16 * QK_STRIDE * 2);
                uint32_t ah[4], al[4];
                ldsm4(ah, sb + QS_AHI + aOff + mo + kOff);
                ldsm4(al, sb + QS_ALO + aOff + mo + kOff);
#pragma unroll
                for (int ni = 0; ni < 4; ni++) {
                    mma_bf16(acc[mi][ni], ah, bh[ni]);
                    mma_bf16(acc[mi][ni], ah, bl[ni]);
                    mma_bf16(acc[mi][ni], al, bh[ni]);
                }
            }
        }
    }

    __syncthreads();
    float* stage = (float*)smem;           // [128][132]
#pragma unroll
    for (int mi = 0; mi < 4; mi++) {
        const int r0 = warpM + mi * 16 + (lane >> 2);
#pragma unroll
        for (int ni = 0; ni < 4; ni++) {
            const int c0 = warpN + ni * 8 + (lane & 3) * 2;
            stage[r0 * 132 + c0]           = acc[mi][ni][0];
            stage[r0 * 132 + c0 + 1]       = acc[mi][ni][1];
            stage[(r0 + 8) * 132 + c0]     = acc[mi][ni][2];
            stage[(r0 + 8) * 132 + c0 + 1] = acc[mi][ni][3];
        }
    }
    __syncthreads();
    float* Cp = out + (size_t)bz * C * NSP + nBase;
#pragma unroll
    for (int it = 0; it < 16; it++) {
        const int idx = it * 256 + tid;
        const int row = idx >> 5, c4 = (idx & 31) << 2;
        const float bb = __ldg(&bout[row]);
        float4 v = *(float4*)&stage[row * 132 + c4];
        v.x += bb; v.y += bb; v.z += bb; v.w += bb;
        *(float4*)&Cp[(size_t)row * NSP + c4] = v;
    }
}

// ============================================================================
extern "C" void kernel_launch(void* const* d_in, const int* in_sizes, int n_in,
                              void* d_out, int out_size) {
    const float* x    = (const float*)d_in[0];
    const float* wqkv = (const float*)d_in[1];
    const float* wout = (const float*)d_in[2];
    const float* bout = (const float*)d_in[3];
    float* out = (float*)d_out;

    cudaFuncSetAttribute(k_qkv_mma, cudaFuncAttributeMaxDynamicSharedMemorySize,
                         QS_TOTAL);
    cudaFuncSetAttribute(k_out_mma, cudaFuncAttributeMaxDynamicSharedMemorySize,
                         QS_TOTAL);

    k_cvt_w  <<<(M3 * C + 255) / 256, 256>>>(wqkv);
    k_cvt_x  <<<dim3(NSP / 32, C / 32, B), dim3(32, 8)>>>(x);
    k_qkv_mma<<<dim3(M3 / 128, NBLK, B), 256, QS_TOTAL>>>();
    k_ctx    <<<dim3(NSPLIT, HEADS, B), 256>>>();
    k_fold   <<<B, 256>>>(wout);
    k_out_mma<<<dim3(NSP / 128, B), 256, QS_TOTAL>>>(out, bout);
}

// round 13
// speedup vs baseline: 1.3292x; 1.2025x over previous
#include <cuda_runtime.h>
#include <cuda_bf16.h>
#include <math.h>
#include <stdint.h>

// Problem constants
#define B      4
#define C      128
#define NSP    32768          // 32*32*32 spatial positions
#define HID    256            // heads * dim_head
#define M3     768            // 3 * HID (qkv rows)
#define HEADS  8
#define DH     32
#define QSCALE 0.17677669529663687f   // 32^-0.5
#define NSPLIT 32
#define NBLK   (NSP / 128)    // 256 n-blocks in the qkv GEMM

// -------- device scratch (static allocation; no cudaMalloc allowed) --------
__device__ float g_ctxp[(size_t)NSPLIT * B * HEADS * DH * DH];
__device__ float g_ksump[(size_t)B * HID * NBLK];        // exp(k) row partials per n-block
// bf16 split operands for tensor-core GEMMs
__device__ __nv_bfloat16 g_xt_hi[(size_t)B * NSP * C];
__device__ __nv_bfloat16 g_xt_lo[(size_t)B * NSP * C];
__device__ __nv_bfloat16 g_w_hi [M3 * C];
__device__ __nv_bfloat16 g_w_lo [M3 * C];
__device__ __nv_bfloat16 g_pt_hi[(size_t)B * NSP * HID]; // softmaxed q^T [b][n][c]
__device__ __nv_bfloat16 g_pt_lo[(size_t)B * NSP * HID];
__device__ __nv_bfloat16 g_ek_hi[(size_t)B * HID * NSP]; // exp(k) [b][row][n]
__device__ __nv_bfloat16 g_ek_lo[(size_t)B * HID * NSP];
__device__ __nv_bfloat16 g_v_hi [(size_t)B * HID * NSP]; // v [b][row][n]
__device__ __nv_bfloat16 g_v_lo [(size_t)B * HID * NSP];
__device__ __nv_bfloat16 g_M_hi [(size_t)B * C * HID];
__device__ __nv_bfloat16 g_M_lo [(size_t)B * C * HID];

// ============================================================================
// warp-MMA helpers (baseline PTX: works on compute_103 target)
// ============================================================================
__device__ __forceinline__ uint32_t smem_u32(const void* p) {
    uint32_t a;
    asm("{ .reg .u64 t; cvta.to.shared.u64 t, %1; cvt.u32.u64 %0, t; }"
        : "=r"(a) : "l"(p));
    return a;
}
__device__ __forceinline__ void ldsm4(uint32_t* r, uint32_t addr) {
    asm volatile("ldmatrix.sync.aligned.m8n8.x4.shared.b16 {%0,%1,%2,%3}, [%4];"
                 : "=r"(r[0]), "=r"(r[1]), "=r"(r[2]), "=r"(r[3]) : "r"(addr));
}
__device__ __forceinline__ void mma_bf16(float* d, const uint32_t* a,
                                         const uint32_t* b) {
    asm volatile(
        "mma.sync.aligned.m16n8k16.row.col.f32.bf16.bf16.f32 "
        "{%0,%1,%2,%3}, {%4,%5,%6,%7}, {%8,%9}, {%0,%1,%2,%3};"
        : "+f"(d[0]), "+f"(d[1]), "+f"(d[2]), "+f"(d[3])
        : "r"(a[0]), "r"(a[1]), "r"(a[2]), "r"(a[3]), "r"(b[0]), "r"(b[1]));
}

// smem layout for the big mma GEMMs; row stride 136 bf16 = 272 B (pad)
#define QK_STRIDE 136
#define QK_TILE_B (128 * QK_STRIDE * 2)
#define QS_AHI 0
#define QS_ALO (QS_AHI + QK_TILE_B)
#define QS_BHI (QS_ALO + QK_TILE_B)
#define QS_BLO (QS_BHI + QK_TILE_B)
#define QS_TOTAL (QS_BLO + QK_TILE_B)       // 139264

// ============================================================================
// conversion kernels: fp32 -> (hi, lo) bf16 split
// ============================================================================
__global__ __launch_bounds__(256) void k_cvt_w(const float* __restrict__ w) {
    const int idx = blockIdx.x * 256 + threadIdx.x;
    if (idx < M3 * C) {
        float v = w[idx];
        __nv_bfloat16 h = __float2bfloat16(v);
        g_w_hi[idx] = h;
        g_w_lo[idx] = __float2bfloat16(v - __bfloat162float(h));
    }
}

// transpose x [b][c][n] fp32 -> x_t [b][n][c] bf16 hi/lo
__global__ __launch_bounds__(256) void k_cvt_x(const float* __restrict__ x) {
    __shared__ float t[32][33];
    const int bz = blockIdx.z;
    const int c0 = blockIdx.y * 32, n0 = blockIdx.x * 32;
    const int tx = threadIdx.x, ty = threadIdx.y;
    const float* xp = x + (size_t)bz * C * NSP;
#pragma unroll
    for (int j = 0; j < 4; j++)
        t[ty + 8 * j][tx] = xp[(size_t)(c0 + ty + 8 * j) * NSP + n0 + tx];
    __syncthreads();
    __nv_bfloat16* oh = g_xt_hi + (size_t)bz * NSP * C;
    __nv_bfloat16* ol = g_xt_lo + (size_t)bz * NSP * C;
#pragma unroll
    for (int j = 0; j < 4; j++) {
        const int n = n0 + ty + 8 * j, c = c0 + tx;
        float v = t[tx][ty + 8 * j];
        __nv_bfloat16 h = __float2bfloat16(v);
        oh[(size_t)n * C + c] = h;
        ol[(size_t)n * C + c] = __float2bfloat16(v - __bfloat162float(h));
    }
}

// ============================================================================
// K1 (tensor core): qkv = w_qkv @ x, bf16 hi/lo (3 chains) + fused epilogues:
//   m-blocks 0,1 (q): transposed stage -> softmax -> coalesced p^T bf16 hi/lo
//   m-blocks 2,3 (k): exp -> g_ek hi/lo bf16 + row partial sums -> g_ksump
//   m-blocks 4,5 (v): -> g_v hi/lo bf16
// grid (6, 256, B), 256 threads (8 warps, 2x4)
// ============================================================================
__global__ __launch_bounds__(256) void k_qkv_mma() {
    extern __shared__ char smem[];
    const int tid = threadIdx.x, wid = tid >> 5, lane = tid & 31;
    const int bz = blockIdx.z;
    const int mBase = blockIdx.x * 128, nBase = blockIdx.y * 128;

    {
        const __nv_bfloat16* xh = g_xt_hi + (size_t)bz * NSP * C;
        const __nv_bfloat16* xl = g_xt_lo + (size_t)bz * NSP * C;
        __nv_bfloat16* sAh = (__nv_bfloat16*)(smem + QS_AHI);
        __nv_bfloat16* sAl = (__nv_bfloat16*)(smem + QS_ALO);
        __nv_bfloat16* sBh = (__nv_bfloat16*)(smem + QS_BHI);
        __nv_bfloat16* sBl = (__nv_bfloat16*)(smem + QS_BLO);
#pragma unroll
        for (int it = 0; it < 8; it++) {
            const int idx = it * 256 + tid;
            const int row = idx >> 4, c8 = (idx & 15) << 3;
            const int so = row * QK_STRIDE + c8;
            const size_t ga = (size_t)(mBase + row) * C + c8;
            const size_t gb = (size_t)(nBase + row) * C + c8;
            *(uint4*)&sAh[so] = *(const uint4*)&g_w_hi[ga];
            *(uint4*)&sAl[so] = *(const uint4*)&g_w_lo[ga];
            *(uint4*)&sBh[so] = *(const uint4*)&xh[gb];
            *(uint4*)&sBl[so] = *(const uint4*)&xl[gb];
        }
    }
    __syncthreads();

    const uint32_t sb = smem_u32(smem);
    const int warpM = (wid >> 2) * 64;
    const int warpN = (wid & 3) * 32;

    const uint32_t aOff =
        (uint32_t)((warpM + (lane & 15)) * QK_STRIDE + ((lane >> 4) << 3)) * 2;
    const int bg = lane >> 3;
    const uint32_t bOff =
        (uint32_t)((warpN + ((bg >> 1) << 3) + (lane & 7)) * QK_STRIDE +
                   ((bg & 1) << 3)) * 2;

    float acc[4][4][4] = {};

#pragma unroll
    for (int ks = 0; ks < 8; ks++) {
        const uint32_t kOff = (uint32_t)ks * 32;
        uint32_t bh[4][2], bl[4][2];
#pragma unroll
        for (int p = 0; p < 2; p++) {
            const uint32_t po = (uint32_t)(p * 16 * QK_STRIDE * 2);
            uint32_t r[4];
            ldsm4(r, sb + QS_BHI + bOff + po + kOff);
            bh[p * 2][0] = r[0]; bh[p * 2][1] = r[1];
            bh[p * 2 + 1][0] = r[2]; bh[p * 2 + 1][1] = r[3];
            ldsm4(r, sb + QS_BLO + bOff + po + kOff);
            bl[p * 2][0] = r[0]; bl[p * 2][1] = r[1];
            bl[p * 2 + 1][0] = r[2]; bl[p * 2 + 1][1] = r[3];
        }
#pragma unroll
        for (int mi = 0; mi < 4; mi++) {
            const uint32_t mo = (uint32_t)(mi * 16 * QK_STRIDE * 2);
            uint32_t ah[4], al[4];
            ldsm4(ah, sb + QS_AHI + aOff + mo + kOff);
            ldsm4(al, sb + QS_ALO + aOff + mo + kOff);
#pragma unroll
            for (int ni = 0; ni < 4; ni++) {
                mma_bf16(acc[mi][ni], ah, bh[ni]);
                mma_bf16(acc[mi][ni], ah, bl[ni]);
                mma_bf16(acc[mi][ni], al, bh[ni]);
            }
        }
    }

    __syncthreads();
    float* stage = (float*)smem;           // [128][132]

    if (blockIdx.x < 2) {
        // ---- q path: transposed stage[n][c]; softmax along contiguous c ----
#pragma unroll
        for (int mi = 0; mi < 4; mi++) {
            const int r0 = warpM + mi * 16 + (lane >> 2);
#pragma unroll
            for (int ni = 0; ni < 4; ni++) {
                const int c0 = warpN + ni * 8 + (lane & 3) * 2;
                stage[c0 * 132 + r0]             = acc[mi][ni][0];
                stage[(c0 + 1) * 132 + r0]       = acc[mi][ni][1];
                stage[c0 * 132 + r0 + 8]         = acc[mi][ni][2];
                stage[(c0 + 1) * 132 + r0 + 8]   = acc[mi][ni][3];
            }
        }
        __syncthreads();
        {
            const int n = tid >> 1;
            float* row = &stage[n * 132];
#pragma unroll
            for (int hh = 0; hh < 2; hh++) {
                const int hg = (tid & 1) * 2 + hh;
                float e[DH];
                float s = 0.f;
#pragma unroll
                for (int j = 0; j < DH; j += 4) {
                    float4 v = *(const float4*)&row[hg * DH + j];
                    e[j] = __expf(v.x); e[j + 1] = __expf(v.y);
                    e[j + 2] = __expf(v.z); e[j + 3] = __expf(v.w);
                    s += e[j] + e[j + 1] + e[j + 2] + e[j + 3];
                }
                const float inv = QSCALE / s;
#pragma unroll
                for (int j = 0; j < DH; j += 4)
                    *(float4*)&row[hg * DH + j] = make_float4(
                        e[j] * inv, e[j + 1] * inv, e[j + 2] * inv, e[j + 3] * inv);
            }
        }
        __syncthreads();
        __nv_bfloat16* ph = g_pt_hi + (size_t)bz * NSP * HID;
        __nv_bfloat16* pl = g_pt_lo + (size_t)bz * NSP * HID;
#pragma unroll
        for (int it = 0; it < 32; it++) {
            const int linear = it * 256 + tid;
            const int n = linear >> 6, c = (linear & 63) * 2;
            const float p0 = stage[n * 132 + c];
            const float p1 = stage[n * 132 + c + 1];
            __nv_bfloat162 h2, l2;
            h2.x = __float2bfloat16(p0);
            h2.y = __float2bfloat16(p1);
            l2.x = __float2bfloat16(p0 - __bfloat162float(h2.x));
            l2.y = __float2bfloat16(p1 - __bfloat162float(h2.y));
            const size_t o = (size_t)(nBase + n) * HID + mBase + c;
            *(__nv_bfloat162*)&ph[o] = h2;
            *(__nv_bfloat162*)&pl[o] = l2;
        }
        return;
    }

    // ---- k / v: normal stage layout ----
#pragma unroll
    for (int mi = 0; mi < 4; mi++) {
        const int r0 = warpM + mi * 16 + (lane >> 2);
#pragma unroll
        for (int ni = 0; ni < 4; ni++) {
            const int c0 = warpN + ni * 8 + (lane & 3) * 2;
            stage[r0 * 132 + c0]           = acc[mi][ni][0];
            stage[r0 * 132 + c0 + 1]       = acc[mi][ni][1];
            stage[(r0 + 8) * 132 + c0]     = acc[mi][ni][2];
            stage[(r0 + 8) * 132 + c0 + 1] = acc[mi][ni][3];
        }
    }
    __syncthreads();

    __nv_bfloat16 *dh, *dl;
    if (blockIdx.x < 4) {
        // k path: exp in place + per-row partial sums
        const int r = tid >> 1, chalf = (tid & 1) * 64;
        float s = 0.f;
#pragma unroll
        for (int c = 0; c < 64; c++) {
            float e = __expf(stage[r * 132 + chalf + c]);
            stage[r * 132 + chalf + c] = e;
            s += e;
        }
        s += __shfl_xor_sync(0xFFFFFFFFu, s, 1);
        if ((tid & 1) == 0) {
            const int kr = (mBase - 256) + r;
            g_ksump[((size_t)bz * HID + kr) * NBLK + blockIdx.y] = s;
        }
        __syncthreads();
        dh = g_ek_hi + ((size_t)bz * HID + (mBase - 256)) * NSP + nBase;
        dl = g_ek_lo + ((size_t)bz * HID + (mBase - 256)) * NSP + nBase;
    } else {
        dh = g_v_hi + ((size_t)bz * HID + (mBase - 512)) * NSP + nBase;
        dl = g_v_lo + ((size_t)bz * HID + (mBase - 512)) * NSP + nBase;
    }

    // hi/lo bf16 split write, coalesced
#pragma unroll
    for (int it = 0; it < 32; it++) {
        const int linear = it * 256 + tid;
        const int row = linear >> 6, cp = (linear & 63) * 2;
        const float p0 = stage[row * 132 + cp];
        const float p1 = stage[row * 132 + cp + 1];
        __nv_bfloat162 h2, l2;
        h2.x = __float2bfloat16(p0);
        h2.y = __float2bfloat16(p1);
        l2.x = __float2bfloat16(p0 - __bfloat162float(h2.x));
        l2.y = __float2bfloat16(p1 - __bfloat162float(h2.y));
        *(__nv_bfloat162*)&dh[(size_t)row * NSP + cp] = h2;
        *(__nv_bfloat162*)&dl[(size_t)row * NSP + cp] = l2;
    }
}

// ============================================================================
// K2 (tensor core): context partials ctx[b,h,d,e] = sum_n ek[d,n] * v[e,n]
// grid (NSPLIT, HEADS, B), 256 threads (8 warps). Each warp owns a 16-wide
// k-slice of a resident 32x128 tile; 2 m-tiles x 4 n-tiles x 3 chains.
// Cross-warp reduce in smem -> g_ctxp.
// ============================================================================
#define CT_ST  136
#define CT_TB  (32 * CT_ST * 2)        // 8704 bytes per tile
#define CT_EH  0
#define CT_EL  (CT_EH + CT_TB)
#define CT_VH  (CT_EL + CT_TB)
#define CT_VL  (CT_VH + CT_TB)
#define CT_SM  (CT_VL + CT_TB)         // 34816; reduce region (33792) reuses it

__global__ __launch_bounds__(256) void k_ctx() {
    __shared__ char sm[CT_SM];
    const int sp = blockIdx.x, h = blockIdx.y, b = blockIdx.z;
    const int tid = threadIdx.x, wid = tid >> 5, lane = tid & 31;
    const size_t rowbase = ((size_t)b * HID + h * DH) * NSP;
    const uint32_t sb = smem_u32(sm);
    const int nb = sp * 1024;

    // fragment addresses (proven recipes; k-column base = wid*16)
    const uint32_t aBase =
        (uint32_t)((lane & 15) * CT_ST + ((lane >> 4) << 3) + wid * 16) * 2;
    const int bg = lane >> 3;
    const uint32_t bBase =
        (uint32_t)((((bg >> 1) << 3) + (lane & 7)) * CT_ST +
                   ((bg & 1) << 3) + wid * 16) * 2;

    float acc[2][4][4] = {};

    for (int t = 0; t < 8; t++) {
        const int n0 = nb + t * 128;
        __syncthreads();
        // cooperative load: 4 tiles of 32x128 bf16
#pragma unroll
        for (int i = 0; i < 2; i++) {
            const int idx = i * 256 + tid;             // 512 uint4 per tile
            const int row = idx >> 4, c8 = (idx & 15) << 3;
            const int so = row * CT_ST + c8;
            const size_t g = rowbase + (size_t)row * NSP + n0 + c8;
            *(uint4*)(sm + CT_EH + so * 2) = *(const uint4*)&g_ek_hi[g];
            *(uint4*)(sm + CT_EL + so * 2) = *(const uint4*)&g_ek_lo[g];
            *(uint4*)(sm + CT_VH + so * 2) = *(const uint4*)&g_v_hi[g];
            *(uint4*)(sm + CT_VL + so * 2) = *(const uint4*)&g_v_lo[g];
        }
        __syncthreads();

        uint32_t ah[2][4], al[2][4];
#pragma unroll
        for (int mt = 0; mt < 2; mt++) {
            const uint32_t mo = (uint32_t)(mt * 16 * CT_ST * 2);
            ldsm4(ah[mt], sb + CT_EH + aBase + mo);
            ldsm4(al[mt], sb + CT_EL + aBase + mo);
        }
        uint32_t bh[4][2], bl[4][2];
#pragma unroll
        for (int p = 0; p < 2; p++) {
            const uint32_t po = (uint32_t)(p * 16 * CT_ST * 2);
            uint32_t r[4];
            ldsm4(r, sb + CT_VH + bBase + po);
            bh[p * 2][0] = r[0]; bh[p * 2][1] = r[1];
            bh[p * 2 + 1][0] = r[2]; bh[p * 2 + 1][1] = r[3];
            ldsm4(r, sb + CT_VL + bBase + po);
            bl[p * 2][0] = r[0]; bl[p * 2][1] = r[1];
            bl[p * 2 + 1][0] = r[2]; bl[p * 2 + 1][1] = r[3];
        }
#pragma unroll
        for (int mt = 0; mt < 2; mt++)
#pragma unroll
            for (int ni = 0; ni < 4; ni++) {
                mma_bf16(acc[mt][ni], ah[mt], bh[ni]);
                mma_bf16(acc[mt][ni], ah[mt], bl[ni]);
                mma_bf16(acc[mt][ni], al[mt], bh[ni]);
            }
    }

    // cross-warp reduce: red[8][32][33]
    __syncthreads();
    float* red = (float*)sm;
#pragma unroll
    for (int mt = 0; mt < 2; mt++)
#pragma unroll
        for (int ni = 0; ni < 4; ni++) {
            const int r0 = mt * 16 + (lane >> 2);
            const int c0 = ni * 8 + (lane & 3) * 2;
            float* wp = red + wid * 1056;
            wp[r0 * 33 + c0]           = acc[mt][ni][0];
            wp[r0 * 33 + c0 + 1]       = acc[mt][ni][1];
            wp[(r0 + 8) * 33 + c0]     = acc[mt][ni][2];
            wp[(r0 + 8) * 33 + c0 + 1] = acc[mt][ni][3];
        }
    __syncthreads();
    float* cp = &g_ctxp[(((size_t)sp * B + b) * HEADS + h) * (DH * DH)];
    for (int idx = tid; idx < DH * DH; idx += 256) {
        const int d = idx >> 5, e = idx & 31;
        float s = 0.f;
#pragma unroll
        for (int w = 0; w < 8; w++) s += red[w * 1056 + d * 33 + e];
        cp[idx] = s;
    }
}

// ============================================================================
// K3: reduce ctx & ksum partials, normalize, fold with w_out -> bf16 hi/lo
// grid B, 256 threads
// ============================================================================
__global__ __launch_bounds__(256) void k_fold(const float* __restrict__ wout) {
    const int b = blockIdx.x;
    __shared__ float ctx[HEADS * DH * DH];
    __shared__ float ks_s[HID];
    const int tid = threadIdx.x;

    {
        const float* kp = &g_ksump[((size_t)b * HID + tid) * NBLK];
        float s = 0.f;
        for (int nb = 0; nb < NBLK; nb += 4) {
            float4 v = *(const float4*)&kp[nb];
            s += v.x + v.y + v.z + v.w;
        }
        ks_s[tid] = s;
    }
    __syncthreads();

    for (int idx = tid; idx < HEADS * DH * DH; idx += 256) {
        float s = 0.f;
        for (int sp = 0; sp < NSPLIT; sp++)
            s += g_ctxp[(((size_t)sp * B + b) * HEADS) * (DH * DH) + idx];
        const int h = idx >> 10, de = idx & 1023, d = de >> 5;
        ctx[idx] = s / ks_s[h * DH + d];
    }
    __syncthreads();

    for (int idx = tid; idx < C * HID; idx += 256) {
        const int o = idx >> 8, cc = idx & 255;
        const int h = cc >> 5, d = cc & 31;
        const float* wrow = &wout[o * HID + h * DH];
        const float* crow = &ctx[h * (DH * DH) + d * 32];
        float s = 0.f;
#pragma unroll
        for (int e = 0; e < DH; e++) s = fmaf(wrow[e], crow[e], s);
        __nv_bfloat16 hh = __float2bfloat16(s);
        g_M_hi[(size_t)b * C * HID + idx] = hh;
        g_M_lo[(size_t)b * C * HID + idx] =
            __float2bfloat16(s - __bfloat162float(hh));
    }
}

// ============================================================================
// K4 (tensor core): out[b][o][n] = sum_c M[o][c] * p[c][n] + bias[o]
// grid (NSP/128, B), 256 threads; K=256 as two resident halves.
// ============================================================================
__global__ __launch_bounds__(256) void k_out_mma(float* __restrict__ out,
                                                const float* __restrict__ bout) {
    extern __shared__ char smem[];
    const int tid = threadIdx.x, wid = tid >> 5, lane = tid & 31;
    const int bz = blockIdx.y;
    const int nBase = blockIdx.x * 128;

    const uint32_t sb = smem_u32(smem);
    const int warpM = (wid >> 2) * 64;
    const int warpN = (wid & 3) * 32;
    const uint32_t aOff =
        (uint32_t)((warpM + (lane & 15)) * QK_STRIDE + ((lane >> 4) << 3)) * 2;
    const int bg = lane >> 3;
    const uint32_t bOff =
        (uint32_t)((warpN + ((bg >> 1) << 3) + (lane & 7)) * QK_STRIDE +
                   ((bg & 1) << 3)) * 2;

    float acc[4][4][4] = {};

    for (int kh = 0; kh < 2; kh++) {
        if (kh) __syncthreads();
        {
            const __nv_bfloat16* mh = g_M_hi + (size_t)bz * C * HID + kh * 128;
            const __nv_bfloat16* ml = g_M_lo + (size_t)bz * C * HID + kh * 128;
            const __nv_bfloat16* ph = g_pt_hi + (size_t)bz * NSP * HID + kh * 128;
            const __nv_bfloat16* pl = g_pt_lo + (size_t)bz * NSP * HID + kh * 128;
            __nv_bfloat16* sAh = (__nv_bfloat16*)(smem + QS_AHI);
            __nv_bfloat16* sAl = (__nv_bfloat16*)(smem + QS_ALO);
            __nv_bfloat16* sBh = (__nv_bfloat16*)(smem + QS_BHI);
            __nv_bfloat16* sBl = (__nv_bfloat16*)(smem + QS_BLO);
#pragma unroll
            for (int it = 0; it < 8; it++) {
                const int idx = it * 256 + tid;
                const int row = idx >> 4, c8 = (idx & 15) << 3;
                const int so = row * QK_STRIDE + c8;
                const size_t ga = (size_t)row * HID + c8;
                const size_t gb = (size_t)(nBase + row) * HID + c8;
                *(uint4*)&sAh[so] = *(const uint4*)&mh[ga];
                *(uint4*)&sAl[so] = *(const uint4*)&ml[ga];
                *(uint4*)&sBh[so] = *(const uint4*)&ph[gb];
                *(uint4*)&sBl[so] = *(const uint4*)&pl[gb];
            }
        }
        __syncthreads();

#pragma unroll
        for (int ks = 0; ks < 8; ks++) {
            const uint32_t kOff = (uint32_t)ks * 32;
            uint32_t bh[4][2], bl[4][2];
#pragma unroll
            for (int p = 0; p < 2; p++) {
                const uint32_t po = (uint32_t)(p * 16 * QK_STRIDE * 2);
                uint32_t r[4];
                ldsm4(r, sb + QS_BHI + bOff + po + kOff);
                bh[p * 2][0] = r[0]; bh[p * 2][1] = r[1];
                bh[p * 2 + 1][0] = r[2]; bh[p * 2 + 1][1] = r[3];
                ldsm4(r, sb + QS_BLO + bOff + po + kOff);
                bl[p * 2][0] = r[0]; bl[p * 2][1] = r[1];
                bl[p * 2 + 1][0] = r[2]; bl[p * 2 + 1][1] = r[3];
            }
#pragma unroll
            for (int mi = 0; mi < 4; mi++) {
                const uint32_t mo = (uint32_t)(mi * 16 * QK_STRIDE * 2);
                uint32_t ah[4], al[4];
                ldsm4(ah, sb + QS_AHI + aOff + mo + kOff);
                ldsm4(al, sb + QS_ALO + aOff + mo + kOff);
#pragma unroll
                for (int ni = 0; ni < 4; ni++) {
                    mma_bf16(acc[mi][ni], ah, bh[ni]);
                    mma_bf16(acc[mi][ni], ah, bl[ni]);
                    mma_bf16(acc[mi][ni], al, bh[ni]);
                }
            }
        }
    }

    __syncthreads();
    float* stage = (float*)smem;           // [128][132]
#pragma unroll
    for (int mi = 0; mi < 4; mi++) {
        const int r0 = warpM + mi * 16 + (lane >> 2);
#pragma unroll
        for (int ni = 0; ni < 4; ni++) {
            const int c0 = warpN + ni * 8 + (lane & 3) * 2;
            stage[r0 * 132 + c0]           = acc[mi][ni][0];
            stage[r0 * 132 + c0 + 1]       = acc[mi][ni][1];
            stage[(r0 + 8) * 132 + c0]     = acc[mi][ni][2];
            stage[(r0 + 8) * 132 + c0 + 1] = acc[mi][ni][3];
        }
    }
    __syncthreads();
    float* Cp = out + (size_t)bz * C * NSP + nBase;
#pragma unroll
    for (int it = 0; it < 16; it++) {
        const int idx = it * 256 + tid;
        const int row = idx >> 5, c4 = (idx & 31) << 2;
        const float bb = __ldg(&bout[row]);
        float4 v = *(float4*)&stage[row * 132 + c4];
        v.x += bb; v.y += bb; v.z += bb; v.w += bb;
        *(float4*)&Cp[(size_t)row * NSP + c4] = v;
    }
}

// ============================================================================
extern "C" void kernel_launch(void* const* d_in, const int* in_sizes, int n_in,
                              void* d_out, int out_size) {
    const float* x    = (const float*)d_in[0];
    const float* wqkv = (const float*)d_in[1];
    const float* wout = (const float*)d_in[2];
    const float* bout = (const float*)d_in[3];
    float* out = (float*)d_out;

    cudaFuncSetAttribute(k_qkv_mma, cudaFuncAttributeMaxDynamicSharedMemorySize,
                         QS_TOTAL);
    cudaFuncSetAttribute(k_out_mma, cudaFuncAttributeMaxDynamicSharedMemorySize,
                         QS_TOTAL);

    k_cvt_w  <<<(M3 * C + 255) / 256, 256>>>(wqkv);
    k_cvt_x  <<<dim3(NSP / 32, C / 32, B), dim3(32, 8)>>>(x);
    k_qkv_mma<<<dim3(M3 / 128, NBLK, B), 256, QS_TOTAL>>>();
    k_ctx    <<<dim3(NSPLIT, HEADS, B), 256>>>();
    k_fold   <<<B, 256>>>(wout);
    k_out_mma<<<dim3(NSP / 128, B), 256, QS_TOTAL>>>(out, bout);
}

// round 14
// speedup vs baseline: 1.3780x; 1.0367x over previous
#include <cuda_runtime.h>
#include <cuda_bf16.h>
#include <math.h>
#include <stdint.h>

// Problem constants
#define B      4
#define C      128
#define NSP    32768          // 32*32*32 spatial positions
#define HID    256            // heads * dim_head
#define M3     768            // 3 * HID (qkv rows)
#define HEADS  8
#define DH     32
#define QSCALE 0.17677669529663687f   // 32^-0.5
#define NSPLIT 32
#define NBLK   (NSP / 64)     // 512 n-blocks in the qkv GEMM (n-tile = 64)

// -------- device scratch (static allocation; no cudaMalloc allowed) --------
__device__ float g_ctxp[(size_t)NSPLIT * B * HEADS * DH * DH];
__device__ float g_ksump[(size_t)B * HID * NBLK];        // exp(k) row partials per n-block
// bf16 split operands for tensor-core GEMMs
__device__ __nv_bfloat16 g_xt_hi[(size_t)B * NSP * C];
__device__ __nv_bfloat16 g_xt_lo[(size_t)B * NSP * C];
__device__ __nv_bfloat16 g_w_hi [M3 * C];
__device__ __nv_bfloat16 g_w_lo [M3 * C];
__device__ __nv_bfloat16 g_pt_hi[(size_t)B * NSP * HID]; // softmaxed q^T [b][n][c]
__device__ __nv_bfloat16 g_pt_lo[(size_t)B * NSP * HID];
__device__ __nv_bfloat16 g_ek_hi[(size_t)B * HID * NSP]; // exp(k) [b][row][n]
__device__ __nv_bfloat16 g_ek_lo[(size_t)B * HID * NSP];
__device__ __nv_bfloat16 g_v_hi [(size_t)B * HID * NSP]; // v [b][row][n]
__device__ __nv_bfloat16 g_v_lo [(size_t)B * HID * NSP];
__device__ __nv_bfloat16 g_M_hi [(size_t)B * C * HID];
__device__ __nv_bfloat16 g_M_lo [(size_t)B * C * HID];

// ============================================================================
// warp-MMA helpers (baseline PTX: works on compute_103 target)
// ============================================================================
__device__ __forceinline__ uint32_t smem_u32(const void* p) {
    uint32_t a;
    asm("{ .reg .u64 t; cvta.to.shared.u64 t, %1; cvt.u32.u64 %0, t; }"
        : "=r"(a) : "l"(p));
    return a;
}
__device__ __forceinline__ void ldsm4(uint32_t* r, uint32_t addr) {
    asm volatile("ldmatrix.sync.aligned.m8n8.x4.shared.b16 {%0,%1,%2,%3}, [%4];"
                 : "=r"(r[0]), "=r"(r[1]), "=r"(r[2]), "=r"(r[3]) : "r"(addr));
}
__device__ __forceinline__ void mma_bf16(float* d, const uint32_t* a,
                                         const uint32_t* b) {
    asm volatile(
        "mma.sync.aligned.m16n8k16.row.col.f32.bf16.bf16.f32 "
        "{%0,%1,%2,%3}, {%4,%5,%6,%7}, {%8,%9}, {%0,%1,%2,%3};"
        : "+f"(d[0]), "+f"(d[1]), "+f"(d[2]), "+f"(d[3])
        : "r"(a[0]), "r"(a[1]), "r"(a[2]), "r"(a[3]), "r"(b[0]), "r"(b[1]));
}

// smem layout for the 128m x 64n MMA kernels; row stride 136 bf16 (272 B pad)
#define QK_STRIDE 136
#define QA_T (128 * QK_STRIDE * 2)      // 34816: A tile 128x128 bf16
#define QB_T (64 * QK_STRIDE * 2)       // 17408: B tile  64x128 bf16
#define QS_AHI 0
#define QS_ALO QA_T
#define QS_BHI (2 * QA_T)
#define QS_BLO (2 * QA_T + QB_T)
#define QS_TOT (2 * QA_T + 2 * QB_T)    // 104448 -> 2 CTAs/SM

// ============================================================================
// conversion kernels: fp32 -> (hi, lo) bf16 split
// ============================================================================
__global__ __launch_bounds__(256) void k_cvt_w(const float* __restrict__ w) {
    const int idx = blockIdx.x * 256 + threadIdx.x;
    if (idx < M3 * C) {
        float v = w[idx];
        __nv_bfloat16 h = __float2bfloat16(v);
        g_w_hi[idx] = h;
        g_w_lo[idx] = __float2bfloat16(v - __bfloat162float(h));
    }
}

// transpose x [b][c][n] fp32 -> x_t [b][n][c] bf16 hi/lo
__global__ __launch_bounds__(256) void k_cvt_x(const float* __restrict__ x) {
    __shared__ float t[32][33];
    const int bz = blockIdx.z;
    const int c0 = blockIdx.y * 32, n0 = blockIdx.x * 32;
    const int tx = threadIdx.x, ty = threadIdx.y;
    const float* xp = x + (size_t)bz * C * NSP;
#pragma unroll
    for (int j = 0; j < 4; j++)
        t[ty + 8 * j][tx] = xp[(size_t)(c0 + ty + 8 * j) * NSP + n0 + tx];
    __syncthreads();
    __nv_bfloat16* oh = g_xt_hi + (size_t)bz * NSP * C;
    __nv_bfloat16* ol = g_xt_lo + (size_t)bz * NSP * C;
#pragma unroll
    for (int j = 0; j < 4; j++) {
        const int n = n0 + ty + 8 * j, c = c0 + tx;
        float v = t[tx][ty + 8 * j];
        __nv_bfloat16 h = __float2bfloat16(v);
        oh[(size_t)n * C + c] = h;
        ol[(size_t)n * C + c] = __float2bfloat16(v - __bfloat162float(h));
    }
}

// ============================================================================
// K1 (tensor core): qkv = w_qkv @ x, bf16 hi/lo (3 chains), 128m x 64n tiles,
// 2 CTAs/SM. Fused epilogues:
//   m-blocks 0,1 (q): transposed stage -> softmax -> coalesced p^T bf16 hi/lo
//   m-blocks 2,3 (k): exp -> g_ek hi/lo + row partial sums -> g_ksump
//   m-blocks 4,5 (v): -> g_v hi/lo
// grid (6, 512, B), 256 threads (8 warps, 2x4); warp tile 64m x 16n
// ============================================================================
__global__ __launch_bounds__(256, 2) void k_qkv_mma() {
    extern __shared__ char smem[];
    const int tid = threadIdx.x, wid = tid >> 5, lane = tid & 31;
    const int bz = blockIdx.z;
    const int mBase = blockIdx.x * 128, nBase = blockIdx.y * 64;

    {
        const __nv_bfloat16* xh = g_xt_hi + (size_t)bz * NSP * C;
        const __nv_bfloat16* xl = g_xt_lo + (size_t)bz * NSP * C;
        __nv_bfloat16* sAh = (__nv_bfloat16*)(smem + QS_AHI);
        __nv_bfloat16* sAl = (__nv_bfloat16*)(smem + QS_ALO);
        __nv_bfloat16* sBh = (__nv_bfloat16*)(smem + QS_BHI);
        __nv_bfloat16* sBl = (__nv_bfloat16*)(smem + QS_BLO);
#pragma unroll
        for (int it = 0; it < 8; it++) {           // A: 2048 uint4
            const int idx = it * 256 + tid;
            const int row = idx >> 4, c8 = (idx & 15) << 3;
            const int so = row * QK_STRIDE + c8;
            const size_t ga = (size_t)(mBase + row) * C + c8;
            *(uint4*)&sAh[so] = *(const uint4*)&g_w_hi[ga];
            *(uint4*)&sAl[so] = *(const uint4*)&g_w_lo[ga];
        }
#pragma unroll
        for (int it = 0; it < 4; it++) {           // B: 1024 uint4
            const int idx = it * 256 + tid;
            const int row = idx >> 4, c8 = (idx & 15) << 3;
            const int so = row * QK_STRIDE + c8;
            const size_t gb = (size_t)(nBase + row) * C + c8;
            *(uint4*)&sBh[so] = *(const uint4*)&xh[gb];
            *(uint4*)&sBl[so] = *(const uint4*)&xl[gb];
        }
    }
    __syncthreads();

    const uint32_t sb = smem_u32(smem);
    const int warpM = (wid >> 2) * 64;     // 0 or 64
    const int warpN = (wid & 3) * 16;      // 0,16,32,48

    const uint32_t aOff =
        (uint32_t)((warpM + (lane & 15)) * QK_STRIDE + ((lane >> 4) << 3)) * 2;
    const int bg = lane >> 3;
    const uint32_t bOff =
        (uint32_t)((warpN + ((bg >> 1) << 3) + (lane & 7)) * QK_STRIDE +
                   ((bg & 1) << 3)) * 2;

    float acc[4][2][4] = {};

#pragma unroll
    for (int ks = 0; ks < 8; ks++) {
        const uint32_t kOff = (uint32_t)ks * 32;
        uint32_t bh[2][2], bl[2][2];
        {
            uint32_t r[4];
            ldsm4(r, sb + QS_BHI + bOff + kOff);
            bh[0][0] = r[0]; bh[0][1] = r[1]; bh[1][0] = r[2]; bh[1][1] = r[3];
            ldsm4(r, sb + QS_BLO + bOff + kOff);
            bl[0][0] = r[0]; bl[0][1] = r[1]; bl[1][0] = r[2]; bl[1][1] = r[3];
        }
#pragma unroll
        for (int mi = 0; mi < 4; mi++) {
            const uint32_t mo = (uint32_t)(mi * 16 * QK_STRIDE * 2);
            uint32_t ah[4], al[4];
            ldsm4(ah, sb + QS_AHI + aOff + mo + kOff);
            ldsm4(al, sb + QS_ALO + aOff + mo + kOff);
#pragma unroll
            for (int ni = 0; ni < 2; ni++) {
                mma_bf16(acc[mi][ni], ah, bh[ni]);
                mma_bf16(acc[mi][ni], ah, bl[ni]);
                mma_bf16(acc[mi][ni], al, bh[ni]);
            }
        }
    }

    __syncthreads();
    float* stage = (float*)smem;

    if (blockIdx.x < 2) {
        // ---- q path: transposed stage[n=64][c=128], stride 132 ----
#pragma unroll
        for (int mi = 0; mi < 4; mi++) {
            const int r0 = warpM + mi * 16 + (lane >> 2);
#pragma unroll
            for (int ni = 0; ni < 2; ni++) {
                const int c0 = warpN + ni * 8 + (lane & 3) * 2;   // n index
                stage[c0 * 132 + r0]             = acc[mi][ni][0];
                stage[(c0 + 1) * 132 + r0]       = acc[mi][ni][1];
                stage[c0 * 132 + r0 + 8]         = acc[mi][ni][2];
                stage[(c0 + 1) * 132 + r0 + 8]   = acc[mi][ni][3];
            }
        }
        __syncthreads();
        {
            // softmax per (n, head-group): n = tid>>2 (0..63), hg = tid&3
            const int n = tid >> 2, hg = tid & 3;
            float* row = &stage[n * 132 + hg * DH];
            float e[DH];
            float s = 0.f;
#pragma unroll
            for (int j = 0; j < DH; j += 4) {
                float4 v = *(const float4*)&row[j];
                e[j] = __expf(v.x); e[j + 1] = __expf(v.y);
                e[j + 2] = __expf(v.z); e[j + 3] = __expf(v.w);
                s += e[j] + e[j + 1] + e[j + 2] + e[j + 3];
            }
            const float inv = QSCALE / s;
#pragma unroll
            for (int j = 0; j < DH; j += 4)
                *(float4*)&row[j] = make_float4(
                    e[j] * inv, e[j + 1] * inv, e[j + 2] * inv, e[j + 3] * inv);
        }
        __syncthreads();
        __nv_bfloat16* ph = g_pt_hi + (size_t)bz * NSP * HID;
        __nv_bfloat16* pl = g_pt_lo + (size_t)bz * NSP * HID;
#pragma unroll
        for (int it = 0; it < 16; it++) {          // 64 n x 128 c = 4096 bf162
            const int linear = it * 256 + tid;
            const int n = linear >> 6, c = (linear & 63) * 2;
            const float p0 = stage[n * 132 + c];
            const float p1 = stage[n * 132 + c + 1];
            __nv_bfloat162 h2, l2;
            h2.x = __float2bfloat16(p0);
            h2.y = __float2bfloat16(p1);
            l2.x = __float2bfloat16(p0 - __bfloat162float(h2.x));
            l2.y = __float2bfloat16(p1 - __bfloat162float(h2.y));
            const size_t o = (size_t)(nBase + n) * HID + mBase + c;
            *(__nv_bfloat162*)&ph[o] = h2;
            *(__nv_bfloat162*)&pl[o] = l2;
        }
        return;
    }

    // ---- k / v: normal stage[m=128][n=64], stride 68 ----
#pragma unroll
    for (int mi = 0; mi < 4; mi++) {
        const int r0 = warpM + mi * 16 + (lane >> 2);
#pragma unroll
        for (int ni = 0; ni < 2; ni++) {
            const int c0 = warpN + ni * 8 + (lane & 3) * 2;
            stage[r0 * 68 + c0]           = acc[mi][ni][0];
            stage[r0 * 68 + c0 + 1]       = acc[mi][ni][1];
            stage[(r0 + 8) * 68 + c0]     = acc[mi][ni][2];
            stage[(r0 + 8) * 68 + c0 + 1] = acc[mi][ni][3];
        }
    }
    __syncthreads();

    __nv_bfloat16 *dh, *dl;
    if (blockIdx.x < 4) {
        // k path: exp in place + per-row partial sums
        const int r = tid >> 1, chalf = (tid & 1) * 32;
        float s = 0.f;
#pragma unroll
        for (int c = 0; c < 32; c++) {
            float e = __expf(stage[r * 68 + chalf + c]);
            stage[r * 68 + chalf + c] = e;
            s += e;
        }
        s += __shfl_xor_sync(0xFFFFFFFFu, s, 1);
        if ((tid & 1) == 0) {
            const int kr = (mBase - 256) + r;
            g_ksump[((size_t)bz * HID + kr) * NBLK + blockIdx.y] = s;
        }
        __syncthreads();
        dh = g_ek_hi + ((size_t)bz * HID + (mBase - 256)) * NSP + nBase;
        dl = g_ek_lo + ((size_t)bz * HID + (mBase - 256)) * NSP + nBase;
    } else {
        dh = g_v_hi + ((size_t)bz * HID + (mBase - 512)) * NSP + nBase;
        dl = g_v_lo + ((size_t)bz * HID + (mBase - 512)) * NSP + nBase;
    }

#pragma unroll
    for (int it = 0; it < 16; it++) {              // 128 x 64 = 4096 bf162
        const int linear = it * 256 + tid;
        const int row = linear >> 5, cp = (linear & 31) * 2;
        const float p0 = stage[row * 68 + cp];
        const float p1 = stage[row * 68 + cp + 1];
        __nv_bfloat162 h2, l2;
        h2.x = __float2bfloat16(p0);
        h2.y = __float2bfloat16(p1);
        l2.x = __float2bfloat16(p0 - __bfloat162float(h2.x));
        l2.y = __float2bfloat16(p1 - __bfloat162float(h2.y));
        *(__nv_bfloat162*)&dh[(size_t)row * NSP + cp] = h2;
        *(__nv_bfloat162*)&dl[(size_t)row * NSP + cp] = l2;
    }
}

// ============================================================================
// K2 (tensor core): context partials ctx[b,h,d,e] = sum_n ek[d,n] * v[e,n]
// grid (NSPLIT, HEADS, B), 256 threads (8 warps), warp = 16-wide k-slice.
// ============================================================================
#define CT_ST  136
#define CT_TB  (32 * CT_ST * 2)
#define CT_EH  0
#define CT_EL  (CT_EH + CT_TB)
#define CT_VH  (CT_EL + CT_TB)
#define CT_VL  (CT_VH + CT_TB)
#define CT_SM  (CT_VL + CT_TB)

__global__ __launch_bounds__(256) void k_ctx() {
    __shared__ char sm[CT_SM];
    const int sp = blockIdx.x, h = blockIdx.y, b = blockIdx.z;
    const int tid = threadIdx.x, wid = tid >> 5, lane = tid & 31;
    const size_t rowbase = ((size_t)b * HID + h * DH) * NSP;
    const uint32_t sb = smem_u32(sm);
    const int nb = sp * 1024;

    const uint32_t aBase =
        (uint32_t)((lane & 15) * CT_ST + ((lane >> 4) << 3) + wid * 16) * 2;
    const int bg = lane >> 3;
    const uint32_t bBase =
        (uint32_t)((((bg >> 1) << 3) + (lane & 7)) * CT_ST +
                   ((bg & 1) << 3) + wid * 16) * 2;

    float acc[2][4][4] = {};

    for (int t = 0; t < 8; t++) {
        const int n0 = nb + t * 128;
        __syncthreads();
#pragma unroll
        for (int i = 0; i < 2; i++) {
            const int idx = i * 256 + tid;
            const int row = idx >> 4, c8 = (idx & 15) << 3;
            const int so = row * CT_ST + c8;
            const size_t g = rowbase + (size_t)row * NSP + n0 + c8;
            *(uint4*)(sm + CT_EH + so * 2) = *(const uint4*)&g_ek_hi[g];
            *(uint4*)(sm + CT_EL + so * 2) = *(const uint4*)&g_ek_lo[g];
            *(uint4*)(sm + CT_VH + so * 2) = *(const uint4*)&g_v_hi[g];
            *(uint4*)(sm + CT_VL + so * 2) = *(const uint4*)&g_v_lo[g];
        }
        __syncthreads();

        uint32_t ah[2][4], al[2][4];
#pragma unroll
        for (int mt = 0; mt < 2; mt++) {
            const uint32_t mo = (uint32_t)(mt * 16 * CT_ST * 2);
            ldsm4(ah[mt], sb + CT_EH + aBase + mo);
            ldsm4(al[mt], sb + CT_EL + aBase + mo);
        }
        uint32_t bh[4][2], bl[4][2];
#pragma unroll
        for (int p = 0; p < 2; p++) {
            const uint32_t po = (uint32_t)(p * 16 * CT_ST * 2);
            uint32_t r[4];
            ldsm4(r, sb + CT_VH + bBase + po);
            bh[p * 2][0] = r[0]; bh[p * 2][1] = r[1];
            bh[p * 2 + 1][0] = r[2]; bh[p * 2 + 1][1] = r[3];
            ldsm4(r, sb + CT_VL + bBase + po);
            bl[p * 2][0] = r[0]; bl[p * 2][1] = r[1];
            bl[p * 2 + 1][0] = r[2]; bl[p * 2 + 1][1] = r[3];
        }
#pragma unroll
        for (int mt = 0; mt < 2; mt++)
#pragma unroll
            for (int ni = 0; ni < 4; ni++) {
                mma_bf16(acc[mt][ni], ah[mt], bh[ni]);
                mma_bf16(acc[mt][ni], ah[mt], bl[ni]);
                mma_bf16(acc[mt][ni], al[mt], bh[ni]);
            }
    }

    __syncthreads();
    float* red = (float*)sm;
#pragma unroll
    for (int mt = 0; mt < 2; mt++)
#pragma unroll
        for (int ni = 0; ni < 4; ni++) {
            const int r0 = mt * 16 + (lane >> 2);
            const int c0 = ni * 8 + (lane & 3) * 2;
            float* wp = red + wid * 1056;
            wp[r0 * 33 + c0]           = acc[mt][ni][0];
            wp[r0 * 33 + c0 + 1]       = acc[mt][ni][1];
            wp[(r0 + 8) * 33 + c0]     = acc[mt][ni][2];
            wp[(r0 + 8) * 33 + c0 + 1] = acc[mt][ni][3];
        }
    __syncthreads();
    float* cp = &g_ctxp[(((size_t)sp * B + b) * HEADS + h) * (DH * DH)];
    for (int idx = tid; idx < DH * DH; idx += 256) {
        const int d = idx >> 5, e = idx & 31;
        float s = 0.f;
#pragma unroll
        for (int w = 0; w < 8; w++) s += red[w * 1056 + d * 33 + e];
        cp[idx] = s;
    }
}

// ============================================================================
// K3: reduce ctx & ksum partials, normalize, fold with w_out -> bf16 hi/lo
// ============================================================================
__global__ __launch_bounds__(256) void k_fold(const float* __restrict__ wout) {
    const int b = blockIdx.x;
    __shared__ float ctx[HEADS * DH * DH];
    __shared__ float ks_s[HID];
    const int tid = threadIdx.x;

    {
        const float* kp = &g_ksump[((size_t)b * HID + tid) * NBLK];
        float s = 0.f;
        for (int nb = 0; nb < NBLK; nb += 4) {
            float4 v = *(const float4*)&kp[nb];
            s += v.x + v.y + v.z + v.w;
        }
        ks_s[tid] = s;
    }
    __syncthreads();

    for (int idx = tid; idx < HEADS * DH * DH; idx += 256) {
        float s = 0.f;
        for (int sp = 0; sp < NSPLIT; sp++)
            s += g_ctxp[(((size_t)sp * B + b) * HEADS) * (DH * DH) + idx];
        const int h = idx >> 10, de = idx & 1023, d = de >> 5;
        ctx[idx] = s / ks_s[h * DH + d];
    }
    __syncthreads();

    for (int idx = tid; idx < C * HID; idx += 256) {
        const int o = idx >> 8, cc = idx & 255;
        const int h = cc >> 5, d = cc & 31;
        const float* wrow = &wout[o * HID + h * DH];
        const float* crow = &ctx[h * (DH * DH) + d * 32];
        float s = 0.f;
#pragma unroll
        for (int e = 0; e < DH; e++) s = fmaf(wrow[e], crow[e], s);
        __nv_bfloat16 hh = __float2bfloat16(s);
        g_M_hi[(size_t)b * C * HID + idx] = hh;
        g_M_lo[(size_t)b * C * HID + idx] =
            __float2bfloat16(s - __bfloat162float(hh));
    }
}

// ============================================================================
// K4 (tensor core): out[b][o][n] = sum_c M[o][c] * p[c][n] + bias[o]
// 128m x 64n tiles, 2 CTAs/SM; K=256 as two halves. grid (512, B)
// ============================================================================
__global__ __launch_bounds__(256, 2) void k_out_mma(float* __restrict__ out,
                                                   const float* __restrict__ bout) {
    extern __shared__ char smem[];
    const int tid = threadIdx.x, wid = tid >> 5, lane = tid & 31;
    const int bz = blockIdx.y;
    const int nBase = blockIdx.x * 64;

    const uint32_t sb = smem_u32(smem);
    const int warpM = (wid >> 2) * 64;
    const int warpN = (wid & 3) * 16;
    const uint32_t aOff =
        (uint32_t)((warpM + (lane & 15)) * QK_STRIDE + ((lane >> 4) << 3)) * 2;
    const int bg = lane >> 3;
    const uint32_t bOff =
        (uint32_t)((warpN + ((bg >> 1) << 3) + (lane & 7)) * QK_STRIDE +
                   ((bg & 1) << 3)) * 2;

    float acc[4][2][4] = {};

    for (int kh = 0; kh < 2; kh++) {
        if (kh) __syncthreads();
        {
            const __nv_bfloat16* mh = g_M_hi + (size_t)bz * C * HID + kh * 128;
            const __nv_bfloat16* ml = g_M_lo + (size_t)bz * C * HID + kh * 128;
            const __nv_bfloat16* ph = g_pt_hi + (size_t)bz * NSP * HID + kh * 128;
            const __nv_bfloat16* pl = g_pt_lo + (size_t)bz * NSP * HID + kh * 128;
            __nv_bfloat16* sAh = (__nv_bfloat16*)(smem + QS_AHI);
            __nv_bfloat16* sAl = (__nv_bfloat16*)(smem + QS_ALO);
            __nv_bfloat16* sBh = (__nv_bfloat16*)(smem + QS_BHI);
            __nv_bfloat16* sBl = (__nv_bfloat16*)(smem + QS_BLO);
#pragma unroll
            for (int it = 0; it < 8; it++) {       // A: 2048 uint4
                const int idx = it * 256 + tid;
                const int row = idx >> 4, c8 = (idx & 15) << 3;
                const int so = row * QK_STRIDE + c8;
                const size_t ga = (size_t)row * HID + c8;
                *(uint4*)&sAh[so] = *(const uint4*)&mh[ga];
                *(uint4*)&sAl[so] = *(const uint4*)&ml[ga];
            }
#pragma unroll
            for (int it = 0; it < 4; it++) {       // B: 1024 uint4
                const int idx = it * 256 + tid;
                const int row = idx >> 4, c8 = (idx & 15) << 3;
                const int so = row * QK_STRIDE + c8;
                const size_t gb = (size_t)(nBase + row) * HID + c8;
                *(uint4*)&sBh[so] = *(const uint4*)&ph[gb];
                *(uint4*)&sBl[so] = *(const uint4*)&pl[gb];
            }
        }
        __syncthreads();

#pragma unroll
        for (int ks = 0; ks < 8; ks++) {
            const uint32_t kOff = (uint32_t)ks * 32;
            uint32_t bh[2][2], bl[2][2];
            {
                uint32_t r[4];
                ldsm4(r, sb + QS_BHI + bOff + kOff);
                bh[0][0] = r[0]; bh[0][1] = r[1]; bh[1][0] = r[2]; bh[1][1] = r[3];
                ldsm4(r, sb + QS_BLO + bOff + kOff);
                bl[0][0] = r[0]; bl[0][1] = r[1]; bl[1][0] = r[2]; bl[1][1] = r[3];
            }
#pragma unroll
            for (int mi = 0; mi < 4; mi++) {
                const uint32_t mo = (uint32_t)(mi * 16 * QK_STRIDE * 2);
                uint32_t ah[4], al[4];
                ldsm4(ah, sb + QS_AHI + aOff + mo + kOff);
                ldsm4(al, sb + QS_ALO + aOff + mo + kOff);
#pragma unroll
                for (int ni = 0; ni < 2; ni++) {
                    mma_bf16(acc[mi][ni], ah, bh[ni]);
                    mma_bf16(acc[mi][ni], ah, bl[ni]);
                    mma_bf16(acc[mi][ni], al, bh[ni]);
                }
            }
        }
    }

    __syncthreads();
    float* stage = (float*)smem;           // [128][68]
#pragma unroll
    for (int mi = 0; mi < 4; mi++) {
        const int r0 = warpM + mi * 16 + (lane >> 2);
#pragma unroll
        for (int ni = 0; ni < 2; ni++) {
            const int c0 = warpN + ni * 8 + (lane & 3) * 2;
            stage[r0 * 68 + c0]           = acc[mi][ni][0];
            stage[r0 * 68 + c0 + 1]       = acc[mi][ni][1];
            stage[(r0 + 8) * 68 + c0]     = acc[mi][ni][2];
            stage[(r0 + 8) * 68 + c0 + 1] = acc[mi][ni][3];
        }
    }
    __syncthreads();
    float* Cp = out + (size_t)bz * C * NSP + nBase;
#pragma unroll
    for (int it = 0; it < 8; it++) {               // 128 x 64 = 2048 float4
        const int idx = it * 256 + tid;
        const int row = idx >> 4, c4 = (idx & 15) << 2;
        const float bb = __ldg(&bout[row]);
        float4 v = *(float4*)&stage[row * 68 + c4];
        v.x += bb; v.y += bb; v.z += bb; v.w += bb;
        *(float4*)&Cp[(size_t)row * NSP + c4] = v;
    }
}

// ============================================================================
extern "C" void kernel_launch(void* const* d_in, const int* in_sizes, int n_in,
                              void* d_out, int out_size) {
    const float* x    = (const float*)d_in[0];
    const float* wqkv = (const float*)d_in[1];
    const float* wout = (const float*)d_in[2];
    const float* bout = (const float*)d_in[3];
    float* out = (float*)d_out;

    cudaFuncSetAttribute(k_qkv_mma, cudaFuncAttributeMaxDynamicSharedMemorySize,
                         QS_TOT);
    cudaFuncSetAttribute(k_out_mma, cudaFuncAttributeMaxDynamicSharedMemorySize,
                         QS_TOT);

    k_cvt_w  <<<(M3 * C + 255) / 256, 256>>>(wqkv);
    k_cvt_x  <<<dim3(NSP / 32, C / 32, B), dim3(32, 8)>>>(x);
    k_qkv_mma<<<dim3(M3 / 128, NBLK, B), 256, QS_TOT>>>();
    k_ctx    <<<dim3(NSPLIT, HEADS, B), 256>>>();
    k_fold   <<<B, 256>>>(wout);
    k_out_mma<<<dim3(NSP / 64, B), 256, QS_TOT>>>(out, bout);
}

// round 16
// speedup vs baseline: 1.4089x; 1.0224x over previous
#include <cuda_runtime.h>
#include <cuda_bf16.h>
#include <math.h>
#include <stdint.h>

// Problem constants
#define B      4
#define C      128
#define NSP    32768          // 32*32*32 spatial positions
#define HID    256            // heads * dim_head
#define M3     768            // 3 * HID (qkv rows)
#define HEADS  8
#define DH     32
#define QSCALE 0.17677669529663687f   // 32^-0.5
#define NSPLIT 32
#define NBLK   (NSP / 64)     // 512 n-blocks (n-tile = 64)

// -------- device scratch (static allocation; no cudaMalloc allowed) --------
__device__ float g_ctxp[(size_t)NSPLIT * B * HEADS * DH * DH];
__device__ float g_ksump[(size_t)B * HID * NBLK];        // exp(k) row partials per n-block
// bf16 split operands for tensor-core GEMMs
__device__ __nv_bfloat16 g_w_hi [M3 * C];
__device__ __nv_bfloat16 g_w_lo [M3 * C];
__device__ __nv_bfloat16 g_pt_hi[(size_t)B * NSP * HID]; // softmaxed q^T [b][n][c]
__device__ __nv_bfloat16 g_pt_lo[(size_t)B * NSP * HID];
__device__ __nv_bfloat16 g_ek_hi[(size_t)B * HID * NSP]; // exp(k) [b][row][n]
__device__ __nv_bfloat16 g_ek_lo[(size_t)B * HID * NSP];
__device__ __nv_bfloat16 g_v_hi [(size_t)B * HID * NSP]; // v [b][row][n]
__device__ __nv_bfloat16 g_v_lo [(size_t)B * HID * NSP];
__device__ __nv_bfloat16 g_M_hi [(size_t)B * C * HID];
__device__ __nv_bfloat16 g_M_lo [(size_t)B * C * HID];

// ============================================================================
// warp-MMA helpers (baseline PTX: works on compute_103 target)
// ============================================================================
__device__ __forceinline__ uint32_t smem_u32(const void* p) {
    uint32_t a;
    asm("{ .reg .u64 t; cvta.to.shared.u64 t, %1; cvt.u32.u64 %0, t; }"
        : "=r"(a) : "l"(p));
    return a;
}
__device__ __forceinline__ void ldsm4(uint32_t* r, uint32_t addr) {
    asm volatile("ldmatrix.sync.aligned.m8n8.x4.shared.b16 {%0,%1,%2,%3}, [%4];"
                 : "=r"(r[0]), "=r"(r[1]), "=r"(r[2]), "=r"(r[3]) : "r"(addr));
}
__device__ __forceinline__ void mma_bf16(float* d, const uint32_t* a,
                                         const uint32_t* b) {
    asm volatile(
        "mma.sync.aligned.m16n8k16.row.col.f32.bf16.bf16.f32 "
        "{%0,%1,%2,%3}, {%4,%5,%6,%7}, {%8,%9}, {%0,%1,%2,%3};"
        : "+f"(d[0]), "+f"(d[1]), "+f"(d[2]), "+f"(d[3])
        : "r"(a[0]), "r"(a[1]), "r"(a[2]), "r"(a[3]), "r"(b[0]), "r"(b[1]));
}

// smem layout for 128m x 64n MMA kernels; row stride 136 bf16 (272 B pad)
#define QK_STRIDE 136
#define QA_T (128 * QK_STRIDE * 2)      // 34816: A tile 128x128 bf16
#define QB_T (64 * QK_STRIDE * 2)       // 17408: B tile  64x128 bf16
#define QS_AHI 0
#define QS_ALO QA_T
#define QS_BHI (2 * QA_T)
#define QS_BLO (2 * QA_T + QB_T)
#define QS_TOT (2 * QA_T + 2 * QB_T)    // 104448 -> 2 CTAs/SM

// ============================================================================
// conversion: w fp32 -> (hi, lo) bf16 split
// ============================================================================
__global__ __launch_bounds__(256) void k_cvt_w(const float* __restrict__ w) {
    const int idx = blockIdx.x * 256 + threadIdx.x;
    if (idx < M3 * C) {
        float v = w[idx];
        __nv_bfloat16 h = __float2bfloat16(v);
        g_w_hi[idx] = h;
        g_w_lo[idx] = __float2bfloat16(v - __bfloat162float(h));
    }
}

// ============================================================================
// K1 (tensor core): qkv = w_qkv @ x. One CTA per n-block; x tile loaded ONCE
// from fp32 input, transposed + hi/lo-split in smem; loop over 6 m-blocks of
// w with fused epilogues:
//   my 0,1 (q): transposed stage -> softmax -> coalesced p^T bf16 hi/lo
//   my 2,3 (k): exp -> g_ek hi/lo + row partial sums -> g_ksump
//   my 4,5 (v): -> g_v hi/lo
// grid (512, B), 256 threads (8 warps, 2x4); warp tile 64m x 16n
// ============================================================================
__global__ __launch_bounds__(256, 2) void k_qkv_mma(const float* __restrict__ x) {
    extern __shared__ char smem[];
    const int tid = threadIdx.x, wid = tid >> 5, lane = tid & 31;
    const int bz = blockIdx.y;
    const int nBase = blockIdx.x * 64;

    // ---- phase 0: stage x tile [128c][64n] fp32 in A region, stride 69 ----
    // (stride 69 is odd -> float4 smem stores would be misaligned; use
    //  scalar stores. gmem read stays vectorized.)
    {
        float* stageX = (float*)smem;
        const float* xp = x + (size_t)bz * C * NSP + nBase;
#pragma unroll
        for (int it = 0; it < 8; it++) {
            const int idx = it * 256 + tid;
            const int c = idx >> 4, n4 = (idx & 15) << 2;
            float4 v = *(const float4*)&xp[(size_t)c * NSP + n4];
            float* d = &stageX[c * 69 + n4];
            d[0] = v.x; d[1] = v.y; d[2] = v.z; d[3] = v.w;
        }
    }
    __syncthreads();

    // ---- phase 1: transpose + hi/lo split into B tiles [64n][128c] ----
    {
        const float* stageX = (const float*)smem;
        __nv_bfloat16* sBh = (__nv_bfloat16*)(smem + QS_BHI);
        __nv_bfloat16* sBl = (__nv_bfloat16*)(smem + QS_BLO);
#pragma unroll
        for (int it = 0; it < 4; it++) {
            const int idx = it * 256 + tid;
            const int n = idx >> 4, c8 = (idx & 15) << 3;
            __nv_bfloat16 hv[8], lv[8];
#pragma unroll
            for (int j = 0; j < 8; j++) {
                float v = stageX[(c8 + j) * 69 + n];
                hv[j] = __float2bfloat16(v);
                lv[j] = __float2bfloat16(v - __bfloat162float(hv[j]));
            }
            const int so = n * QK_STRIDE + c8;
            *(uint4*)&sBh[so] = *(const uint4*)hv;
            *(uint4*)&sBl[so] = *(const uint4*)lv;
        }
    }

    const uint32_t sb = smem_u32(smem);
    const int warpM = (wid >> 2) * 64;     // 0 or 64
    const int warpN = (wid & 3) * 16;      // 0,16,32,48
    const uint32_t aOff =
        (uint32_t)((warpM + (lane & 15)) * QK_STRIDE + ((lane >> 4) << 3)) * 2;
    const int bg = lane >> 3;
    const uint32_t bOff =
        (uint32_t)((warpN + ((bg >> 1) << 3) + (lane & 7)) * QK_STRIDE +
                   ((bg & 1) << 3)) * 2;

    __nv_bfloat16* sAh = (__nv_bfloat16*)(smem + QS_AHI);
    __nv_bfloat16* sAl = (__nv_bfloat16*)(smem + QS_ALO);
    float* stage = (float*)smem;

    for (int my = 0; my < 6; my++) {
        __syncthreads();   // stage/stageX reads of previous phase done
        // ---- load A (w m-block) hi/lo ----
#pragma unroll
        for (int it = 0; it < 8; it++) {
            const int idx = it * 256 + tid;
            const int row = idx >> 4, c8 = (idx & 15) << 3;
            const int so = row * QK_STRIDE + c8;
            const size_t ga = (size_t)(my * 128 + row) * C + c8;
            *(uint4*)&sAh[so] = *(const uint4*)&g_w_hi[ga];
            *(uint4*)&sAl[so] = *(const uint4*)&g_w_lo[ga];
        }
        __syncthreads();

        float acc[4][2][4] = {};
#pragma unroll
        for (int ks = 0; ks < 8; ks++) {
            const uint32_t kOff = (uint32_t)ks * 32;
            uint32_t bh[2][2], bl[2][2];
            {
                uint32_t r[4];
                ldsm4(r, sb + QS_BHI + bOff + kOff);
                bh[0][0] = r[0]; bh[0][1] = r[1]; bh[1][0] = r[2]; bh[1][1] = r[3];
                ldsm4(r, sb + QS_BLO + bOff + kOff);
                bl[0][0] = r[0]; bl[0][1] = r[1]; bl[1][0] = r[2]; bl[1][1] = r[3];
            }
#pragma unroll
            for (int mi = 0; mi < 4; mi++) {
                const uint32_t mo = (uint32_t)(mi * 16 * QK_STRIDE * 2);
                uint32_t ah[4], al[4];
                ldsm4(ah, sb + QS_AHI + aOff + mo + kOff);
                ldsm4(al, sb + QS_ALO + aOff + mo + kOff);
#pragma unroll
                for (int ni = 0; ni < 2; ni++) {
                    mma_bf16(acc[mi][ni], ah, bh[ni]);
                    mma_bf16(acc[mi][ni], ah, bl[ni]);
                    mma_bf16(acc[mi][ni], al, bh[ni]);
                }
            }
        }
        __syncthreads();   // A reads done; stage (overlapping A) safe to write

        if (my < 2) {
            // ---- q: transposed stage[n=64][c=128], stride 132 ----
#pragma unroll
            for (int mi = 0; mi < 4; mi++) {
                const int r0 = warpM + mi * 16 + (lane >> 2);
#pragma unroll
                for (int ni = 0; ni < 2; ni++) {
                    const int c0 = warpN + ni * 8 + (lane & 3) * 2;   // n index
                    stage[c0 * 132 + r0]             = acc[mi][ni][0];
                    stage[(c0 + 1) * 132 + r0]       = acc[mi][ni][1];
                    stage[c0 * 132 + r0 + 8]         = acc[mi][ni][2];
                    stage[(c0 + 1) * 132 + r0 + 8]   = acc[mi][ni][3];
                }
            }
            __syncthreads();
            {
                // softmax per (n, head-group): n = tid>>2 (0..63), hg = tid&3
                const int n = tid >> 2, hg = tid & 3;
                float* row = &stage[n * 132 + hg * DH];
                float e[DH];
                float s = 0.f;
#pragma unroll
                for (int j = 0; j < DH; j += 4) {
                    float4 v = *(const float4*)&row[j];
                    e[j] = __expf(v.x); e[j + 1] = __expf(v.y);
                    e[j + 2] = __expf(v.z); e[j + 3] = __expf(v.w);
                    s += e[j] + e[j + 1] + e[j + 2] + e[j + 3];
                }
                const float inv = QSCALE / s;
#pragma unroll
                for (int j = 0; j < DH; j += 4)
                    *(float4*)&row[j] = make_float4(
                        e[j] * inv, e[j + 1] * inv, e[j + 2] * inv, e[j + 3] * inv);
            }
            __syncthreads();
            __nv_bfloat16* ph = g_pt_hi + (size_t)bz * NSP * HID;
            __nv_bfloat16* pl = g_pt_lo + (size_t)bz * NSP * HID;
#pragma unroll
            for (int it = 0; it < 16; it++) {      // 64 n x 128 c = 4096 bf162
                const int linear = it * 256 + tid;
                const int n = linear >> 6, c = (linear & 63) * 2;
                const float p0 = stage[n * 132 + c];
                const float p1 = stage[n * 132 + c + 1];
                __nv_bfloat162 h2, l2;
                h2.x = __float2bfloat16(p0);
                h2.y = __float2bfloat16(p1);
                l2.x = __float2bfloat16(p0 - __bfloat162float(h2.x));
                l2.y = __float2bfloat16(p1 - __bfloat162float(h2.y));
                const size_t o = (size_t)(nBase + n) * HID + my * 128 + c;
                *(__nv_bfloat162*)&ph[o] = h2;
                *(__nv_bfloat162*)&pl[o] = l2;
            }
        } else {
            // ---- k / v: normal stage[m=128][n=64], stride 68 ----
#pragma unroll
            for (int mi = 0; mi < 4; mi++) {
                const int r0 = warpM + mi * 16 + (lane >> 2);
#pragma unroll
                for (int ni = 0; ni < 2; ni++) {
                    const int c0 = warpN + ni * 8 + (lane & 3) * 2;
                    stage[r0 * 68 + c0]           = acc[mi][ni][0];
                    stage[r0 * 68 + c0 + 1]       = acc[mi][ni][1];
                    stage[(r0 + 8) * 68 + c0]     = acc[mi][ni][2];
                    stage[(r0 + 8) * 68 + c0 + 1] = acc[mi][ni][3];
                }
            }
            __syncthreads();

            __nv_bfloat16 *dh, *dl;
            if (my < 4) {
                // k path: exp in place + per-row partial sums
                const int r = tid >> 1, chalf = (tid & 1) * 32;
                float s = 0.f;
#pragma unroll
                for (int c = 0; c < 32; c++) {
                    float e = __expf(stage[r * 68 + chalf + c]);
                    stage[r * 68 + chalf + c] = e;
                    s += e;
                }
                s += __shfl_xor_sync(0xFFFFFFFFu, s, 1);
                if ((tid & 1) == 0) {
                    const int kr = (my - 2) * 128 + r;
                    g_ksump[((size_t)bz * HID + kr) * NBLK + blockIdx.x] = s;
                }
                __syncthreads();
                dh = g_ek_hi + ((size_t)bz * HID + (my - 2) * 128) * NSP + nBase;
                dl = g_ek_lo + ((size_t)bz * HID + (my - 2) * 128) * NSP + nBase;
            } else {
                dh = g_v_hi + ((size_t)bz * HID + (my - 4) * 128) * NSP + nBase;
                dl = g_v_lo + ((size_t)bz * HID + (my - 4) * 128) * NSP + nBase;
            }

#pragma unroll
            for (int it = 0; it < 16; it++) {      // 128 x 64 = 4096 bf162
                const int linear = it * 256 + tid;
                const int row = linear >> 5, cp = (linear & 31) * 2;
                const float p0 = stage[row * 68 + cp];
                const float p1 = stage[row * 68 + cp + 1];
                __nv_bfloat162 h2, l2;
                h2.x = __float2bfloat16(p0);
                h2.y = __float2bfloat16(p1);
                l2.x = __float2bfloat16(p0 - __bfloat162float(h2.x));
                l2.y = __float2bfloat16(p1 - __bfloat162float(h2.y));
                *(__nv_bfloat162*)&dh[(size_t)row * NSP + cp] = h2;
                *(__nv_bfloat162*)&dl[(size_t)row * NSP + cp] = l2;
            }
        }
    }
}

// ============================================================================
// K2 (tensor core): context partials ctx[b,h,d,e] = sum_n ek[d,n] * v[e,n]
// grid (NSPLIT, HEADS, B), 256 threads (8 warps), warp = 16-wide k-slice.
// ============================================================================
#define CT_ST  136
#define CT_TB  (32 * CT_ST * 2)
#define CT_EH  0
#define CT_EL  (CT_EH + CT_TB)
#define CT_VH  (CT_EL + CT_TB)
#define CT_VL  (CT_VH + CT_TB)
#define CT_SM  (CT_VL + CT_TB)

__global__ __launch_bounds__(256) void k_ctx() {
    __shared__ char sm[CT_SM];
    const int sp = blockIdx.x, h = blockIdx.y, b = blockIdx.z;
    const int tid = threadIdx.x, wid = tid >> 5, lane = tid & 31;
    const size_t rowbase = ((size_t)b * HID + h * DH) * NSP;
    const uint32_t sb = smem_u32(sm);
    const int nb = sp * 1024;

    const uint32_t aBase =
        (uint32_t)((lane & 15) * CT_ST + ((lane >> 4) << 3) + wid * 16) * 2;
    const int bg = lane >> 3;
    const uint32_t bBase =
        (uint32_t)((((bg >> 1) << 3) + (lane & 7)) * CT_ST +
                   ((bg & 1) << 3) + wid * 16) * 2;

    float acc[2][4][4] = {};

    for (int t = 0; t < 8; t++) {
        const int n0 = nb + t * 128;
        __syncthreads();
#pragma unroll
        for (int i = 0; i < 2; i++) {
            const int idx = i * 256 + tid;
            const int row = idx >> 4, c8 = (idx & 15) << 3;
            const int so = row * CT_ST + c8;
            const size_t g = rowbase + (size_t)row * NSP + n0 + c8;
            *(uint4*)(sm + CT_EH + so * 2) = *(const uint4*)&g_ek_hi[g];
            *(uint4*)(sm + CT_EL + so * 2) = *(const uint4*)&g_ek_lo[g];
            *(uint4*)(sm + CT_VH + so * 2) = *(const uint4*)&g_v_hi[g];
            *(uint4*)(sm + CT_VL + so * 2) = *(const uint4*)&g_v_lo[g];
        }
        __syncthreads();

        uint32_t ah[2][4], al[2][4];
#pragma unroll
        for (int mt = 0; mt < 2; mt++) {
            const uint32_t mo = (uint32_t)(mt * 16 * CT_ST * 2);
            ldsm4(ah[mt], sb + CT_EH + aBase + mo);
            ldsm4(al[mt], sb + CT_EL + aBase + mo);
        }
        uint32_t bh[4][2], bl[4][2];
#pragma unroll
        for (int p = 0; p < 2; p++) {
            const uint32_t po = (uint32_t)(p * 16 * CT_ST * 2);
            uint32_t r[4];
            ldsm4(r, sb + CT_VH + bBase + po);
            bh[p * 2][0] = r[0]; bh[p * 2][1] = r[1];
            bh[p * 2 + 1][0] = r[2]; bh[p * 2 + 1][1] = r[3];
            ldsm4(r, sb + CT_VL + bBase + po);
            bl[p * 2][0] = r[0]; bl[p * 2][1] = r[1];
            bl[p * 2 + 1][0] = r[2]; bl[p * 2 + 1][1] = r[3];
        }
#pragma unroll
        for (int mt = 0; mt < 2; mt++)
#pragma unroll
            for (int ni = 0; ni < 4; ni++) {
                mma_bf16(acc[mt][ni], ah[mt], bh[ni]);
                mma_bf16(acc[mt][ni], ah[mt], bl[ni]);
                mma_bf16(acc[mt][ni], al[mt], bh[ni]);
            }
    }

    __syncthreads();
    float* red = (float*)sm;
#pragma unroll
    for (int mt = 0; mt < 2; mt++)
#pragma unroll
        for (int ni = 0; ni < 4; ni++) {
            const int r0 = mt * 16 + (lane >> 2);
            const int c0 = ni * 8 + (lane & 3) * 2;
            float* wp = red + wid * 1056;
            wp[r0 * 33 + c0]           = acc[mt][ni][0];
            wp[r0 * 33 + c0 + 1]       = acc[mt][ni][1];
            wp[(r0 + 8) * 33 + c0]     = acc[mt][ni][2];
            wp[(r0 + 8) * 33 + c0 + 1] = acc[mt][ni][3];
        }
    __syncthreads();
    float* cp = &g_ctxp[(((size_t)sp * B + b) * HEADS + h) * (DH * DH)];
    for (int idx = tid; idx < DH * DH; idx += 256) {
        const int d = idx >> 5, e = idx & 31;
        float s = 0.f;
#pragma unroll
        for (int w = 0; w < 8; w++) s += red[w * 1056 + d * 33 + e];
        cp[idx] = s;
    }
}

// ============================================================================
// K3: reduce ctx & ksum partials, normalize, fold with w_out -> bf16 hi/lo
// ============================================================================
__global__ __launch_bounds__(256) void k_fold(const float* __restrict__ wout) {
    const int b = blockIdx.x;
    __shared__ float ctx[HEADS * DH * DH];
    __shared__ float ks_s[HID];
    const int tid = threadIdx.x;

    {
        const float* kp = &g_ksump[((size_t)b * HID + tid) * NBLK];
        float s = 0.f;
        for (int nb = 0; nb < NBLK; nb += 4) {
            float4 v = *(const float4*)&kp[nb];
            s += v.x + v.y + v.z + v.w;
        }
        ks_s[tid] = s;
    }
    __syncthreads();

    for (int idx = tid; idx < HEADS * DH * DH; idx += 256) {
        float s = 0.f;
        for (int sp = 0; sp < NSPLIT; sp++)
            s += g_ctxp[(((size_t)sp * B + b) * HEADS) * (DH * DH) + idx];
        const int h = idx >> 10, de = idx & 1023, d = de >> 5;
        ctx[idx] = s / ks_s[h * DH + d];
    }
    __syncthreads();

    for (int idx = tid; idx < C * HID; idx += 256) {
        const int o = idx >> 8, cc = idx & 255;
        const int h = cc >> 5, d = cc & 31;
        const float* wrow = &wout[o * HID + h * DH];
        const float* crow = &ctx[h * (DH * DH) + d * 32];
        float s = 0.f;
#pragma unroll
        for (int e = 0; e < DH; e++) s = fmaf(wrow[e], crow[e], s);
        __nv_bfloat16 hh = __float2bfloat16(s);
        g_M_hi[(size_t)b * C * HID + idx] = hh;
        g_M_lo[(size_t)b * C * HID + idx] =
            __float2bfloat16(s - __bfloat162float(hh));
    }
}

// ============================================================================
// K4 (tensor core): out[b][o][n] = sum_c M[o][c] * p[c][n] + bias[o]
// 128m x 64n tiles, 2 CTAs/SM; K=256 as two halves. grid (512, B)
// ============================================================================
__global__ __launch_bounds__(256, 2) void k_out_mma(float* __restrict__ out,
                                                   const float* __restrict__ bout) {
    extern __shared__ char smem[];
    const int tid = threadIdx.x, wid = tid >> 5, lane = tid & 31;
    const int bz = blockIdx.y;
    const int nBase = blockIdx.x * 64;

    const uint32_t sb = smem_u32(smem);
    const int warpM = (wid >> 2) * 64;
    const int warpN = (wid & 3) * 16;
    const uint32_t aOff =
        (uint32_t)((warpM + (lane & 15)) * QK_STRIDE + ((lane >> 4) << 3)) * 2;
    const int bg = lane >> 3;
    const uint32_t bOff =
        (uint32_t)((warpN + ((bg >> 1) << 3) + (lane & 7)) * QK_STRIDE +
                   ((bg & 1) << 3)) * 2;

    float acc[4][2][4] = {};

    for (int kh = 0; kh < 2; kh++) {
        if (kh) __syncthreads();
        {
            const __nv_bfloat16* mh = g_M_hi + (size_t)bz * C * HID + kh * 128;
            const __nv_bfloat16* ml = g_M_lo + (size_t)bz * C * HID + kh * 128;
            const __nv_bfloat16* ph = g_pt_hi + (size_t)bz * NSP * HID + kh * 128;
            const __nv_bfloat16* pl = g_pt_lo + (size_t)bz * NSP * HID + kh * 128;
            __nv_bfloat16* sAh = (__nv_bfloat16*)(smem + QS_AHI);
            __nv_bfloat16* sAl = (__nv_bfloat16*)(smem + QS_ALO);
            __nv_bfloat16* sBh = (__nv_bfloat16*)(smem + QS_BHI);
            __nv_bfloat16* sBl = (__nv_bfloat16*)(smem + QS_BLO);
#pragma unroll
            for (int it = 0; it < 8; it++) {       // A: 2048 uint4
                const int idx = it * 256 + tid;
                const int row = idx >> 4, c8 = (idx & 15) << 3;
                const int so = row * QK_STRIDE + c8;
                const size_t ga = (size_t)row * HID + c8;
                *(uint4*)&sAh[so] = *(const uint4*)&mh[ga];
                *(uint4*)&sAl[so] = *(const uint4*)&ml[ga];
            }
#pragma unroll
            for (int it = 0; it < 4; it++) {       // B: 1024 uint4
                const int idx = it * 256 + tid;
                const int row = idx >> 4, c8 = (idx & 15) << 3;
                const int so = row * QK_STRIDE + c8;
                const size_t gb = (size_t)(nBase + row) * HID + c8;
                *(uint4*)&sBh[so] = *(const uint4*)&ph[gb];
                *(uint4*)&sBl[so] = *(const uint4*)&pl[gb];
            }
        }
        __syncthreads();

#pragma unroll
        for (int ks = 0; ks < 8; ks++) {
            const uint32_t kOff = (uint32_t)ks * 32;
            uint32_t bh[2][2], bl[2][2];
            {
                uint32_t r[4];
                ldsm4(r, sb + QS_BHI + bOff + kOff);
                bh[0][0] = r[0]; bh[0][1] = r[1]; bh[1][0] = r[2]; bh[1][1] = r[3];
                ldsm4(r, sb + QS_BLO + bOff + kOff);
                bl[0][0] = r[0]; bl[0][1] = r[1]; bl[1][0] = r[2]; bl[1][1] = r[3];
            }
#pragma unroll
            for (int mi = 0; mi < 4; mi++) {
                const uint32_t mo = (uint32_t)(mi * 16 * QK_STRIDE * 2);
                uint32_t ah[4], al[4];
                ldsm4(ah, sb + QS_AHI + aOff + mo + kOff);
                ldsm4(al, sb + QS_ALO + aOff + mo + kOff);
#pragma unroll
                for (int ni = 0; ni < 2; ni++) {
                    mma_bf16(acc[mi][ni], ah, bh[ni]);
                    mma_bf16(acc[mi][ni], ah, bl[ni]);
                    mma_bf16(acc[mi][ni], al, bh[ni]);
                }
            }
        }
    }

    __syncthreads();
    float* stage = (float*)smem;           // [128][68]
#pragma unroll
    for (int mi = 0; mi < 4; mi++) {
        const int r0 = warpM + mi * 16 + (lane >> 2);
#pragma unroll
        for (int ni = 0; ni < 2; ni++) {
            const int c0 = warpN + ni * 8 + (lane & 3) * 2;
            stage[r0 * 68 + c0]           = acc[mi][ni][0];
            stage[r0 * 68 + c0 + 1]       = acc[mi][ni][1];
            stage[(r0 + 8) * 68 + c0]     = acc[mi][ni][2];
            stage[(r0 + 8) * 68 + c0 + 1] = acc[mi][ni][3];
        }
    }
    __syncthreads();
    float* Cp = out + (size_t)bz * C * NSP + nBase;
#pragma unroll
    for (int it = 0; it < 8; it++) {               // 128 x 64 = 2048 float4
        const int idx = it * 256 + tid;
        const int row = idx >> 4, c4 = (idx & 15) << 2;
        const float bb = __ldg(&bout[row]);
        float4 v = *(float4*)&stage[row * 68 + c4];
        v.x += bb; v.y += bb; v.z += bb; v.w += bb;
        *(float4*)&Cp[(size_t)row * NSP + c4] = v;
    }
}

// ============================================================================
extern "C" void kernel_launch(void* const* d_in, const int* in_sizes, int n_in,
                              void* d_out, int out_size) {
    const float* x    = (const float*)d_in[0];
    const float* wqkv = (const float*)d_in[1];
    const float* wout = (const float*)d_in[2];
    const float* bout = (const float*)d_in[3];
    float* out = (float*)d_out;

    cudaFuncSetAttribute(k_qkv_mma, cudaFuncAttributeMaxDynamicSharedMemorySize,
                         QS_TOT);
    cudaFuncSetAttribute(k_out_mma, cudaFuncAttributeMaxDynamicSharedMemorySize,
                         QS_TOT);

    k_cvt_w  <<<(M3 * C + 255) / 256, 256>>>(wqkv);
    k_qkv_mma<<<dim3(NBLK, B), 256, QS_TOT>>>(x);
    k_ctx    <<<dim3(NSPLIT, HEADS, B), 256>>>();
    k_fold   <<<B, 256>>>(wout);
    k_out_mma<<<dim3(NSP / 64, B), 256, QS_TOT>>>(out, bout);
}

// round 17
// speedup vs baseline: 1.8154x; 1.2885x over previous
#include <cuda_runtime.h>
#include <cuda_bf16.h>
#include <math.h>
#include <stdint.h>

// Problem constants
#define B      4
#define C      128
#define NSP    32768          // 32*32*32 spatial positions
#define HID    256            // heads * dim_head
#define M3     768            // 3 * HID (qkv rows)
#define HEADS  8
#define DH     32
#define QSCALE 0.17677669529663687f   // 32^-0.5
#define NSPLIT 32
#define NBLK   (NSP / 64)     // 512 n-blocks (n-tile = 64)

// -------- device scratch (static allocation; no cudaMalloc allowed) --------
__device__ float g_ctxp[(size_t)NSPLIT * B * HEADS * DH * DH];
__device__ float g_ksump[(size_t)B * HID * NBLK];        // exp(k) row partials per n-block
// bf16 split operands for tensor-core GEMMs
__device__ __nv_bfloat16 g_w_hi [M3 * C];
__device__ __nv_bfloat16 g_w_lo [M3 * C];
__device__ __nv_bfloat16 g_pt_hi[(size_t)B * NSP * HID]; // softmaxed q^T [b][n][c]
__device__ __nv_bfloat16 g_pt_lo[(size_t)B * NSP * HID];
__device__ __nv_bfloat16 g_ek_hi[(size_t)B * HID * NSP]; // exp(k) [b][row][n]
__device__ __nv_bfloat16 g_ek_lo[(size_t)B * HID * NSP];
__device__ __nv_bfloat16 g_v_hi [(size_t)B * HID * NSP]; // v [b][row][n]
__device__ __nv_bfloat16 g_v_lo [(size_t)B * HID * NSP];
__device__ __nv_bfloat16 g_M_hi [(size_t)B * C * HID];
__device__ __nv_bfloat16 g_M_lo [(size_t)B * C * HID];

// ============================================================================
// warp-MMA helpers (baseline PTX: works on compute_103 target)
// ============================================================================
__device__ __forceinline__ uint32_t smem_u32(const void* p) {
    uint32_t a;
    asm("{ .reg .u64 t; cvta.to.shared.u64 t, %1; cvt.u32.u64 %0, t; }"
        : "=r"(a) : "l"(p));
    return a;
}
__device__ __forceinline__ void ldsm4(uint32_t* r, uint32_t addr) {
    asm volatile("ldmatrix.sync.aligned.m8n8.x4.shared.b16 {%0,%1,%2,%3}, [%4];"
                 : "=r"(r[0]), "=r"(r[1]), "=r"(r[2]), "=r"(r[3]) : "r"(addr));
}
__device__ __forceinline__ void mma_bf16(float* d, const uint32_t* a,
                                         const uint32_t* b) {
    asm volatile(
        "mma.sync.aligned.m16n8k16.row.col.f32.bf16.bf16.f32 "
        "{%0,%1,%2,%3}, {%4,%5,%6,%7}, {%8,%9}, {%0,%1,%2,%3};"
        : "+f"(d[0]), "+f"(d[1]), "+f"(d[2]), "+f"(d[3])
        : "r"(a[0]), "r"(a[1]), "r"(a[2]), "r"(a[3]), "r"(b[0]), "r"(b[1]));
}

// smem layout for 128m x 64n MMA kernels; row stride 136 bf16 (272 B pad)
#define QK_STRIDE 136
#define QA_T (128 * QK_STRIDE * 2)      // 34816: A tile 128x128 bf16
#define QB_T (64 * QK_STRIDE * 2)       // 17408: B tile  64x128 bf16
#define QS_AHI 0
#define QS_ALO QA_T
#define QS_BHI (2 * QA_T)
#define QS_BLO (2 * QA_T + QB_T)
#define QS_TOT (2 * QA_T + 2 * QB_T)    // 104448 -> 2 CTAs/SM

// ============================================================================
// conversion: w fp32 -> (hi, lo) bf16 split
// ============================================================================
__global__ __launch_bounds__(256) void k_cvt_w(const float* __restrict__ w) {
    const int idx = blockIdx.x * 256 + threadIdx.x;
    if (idx < M3 * C) {
        float v = w[idx];
        __nv_bfloat16 h = __float2bfloat16(v);
        g_w_hi[idx] = h;
        g_w_lo[idx] = __float2bfloat16(v - __bfloat162float(h));
    }
}

// ============================================================================
// K1 (tensor core): qkv = w_qkv @ x. One CTA per n-block; x tile loaded ONCE
// from fp32 input, transposed + hi/lo-split in smem; loop over 6 m-blocks of
// w with fused epilogues:
//   my 0,1 (q): transposed stage -> softmax -> coalesced p^T bf16 hi/lo
//   my 2,3 (k): exp -> g_ek hi/lo + row partial sums -> g_ksump
//   my 4,5 (v): -> g_v hi/lo
// grid (512, B), 256 threads (8 warps, 2x4); warp tile 64m x 16n
// ============================================================================
__global__ __launch_bounds__(256, 2) void k_qkv_mma(const float* __restrict__ x) {
    extern __shared__ char smem[];
    const int tid = threadIdx.x, wid = tid >> 5, lane = tid & 31;
    const int bz = blockIdx.y;
    const int nBase = blockIdx.x * 64;

    // ---- phase 0: stage x tile [128c][64n] fp32 in A region, stride 69 ----
    // (stride 69 is odd -> float4 smem stores would be misaligned; scalar STS)
    {
        float* stageX = (float*)smem;
        const float* xp = x + (size_t)bz * C * NSP + nBase;
#pragma unroll
        for (int it = 0; it < 8; it++) {
            const int idx = it * 256 + tid;
            const int c = idx >> 4, n4 = (idx & 15) << 2;
            float4 v = *(const float4*)&xp[(size_t)c * NSP + n4];
            float* d = &stageX[c * 69 + n4];
            d[0] = v.x; d[1] = v.y; d[2] = v.z; d[3] = v.w;
        }
    }
    __syncthreads();

    // ---- phase 1: transpose + hi/lo split into B tiles [64n][128c] ----
    {
        const float* stageX = (const float*)smem;
        __nv_bfloat16* sBh = (__nv_bfloat16*)(smem + QS_BHI);
        __nv_bfloat16* sBl = (__nv_bfloat16*)(smem + QS_BLO);
#pragma unroll
        for (int it = 0; it < 4; it++) {
            const int idx = it * 256 + tid;
            const int n = idx >> 4, c8 = (idx & 15) << 3;
            __nv_bfloat16 hv[8], lv[8];
#pragma unroll
            for (int j = 0; j < 8; j++) {
                float v = stageX[(c8 + j) * 69 + n];
                hv[j] = __float2bfloat16(v);
                lv[j] = __float2bfloat16(v - __bfloat162float(hv[j]));
            }
            const int so = n * QK_STRIDE + c8;
            *(uint4*)&sBh[so] = *(const uint4*)hv;
            *(uint4*)&sBl[so] = *(const uint4*)lv;
        }
    }

    const uint32_t sb = smem_u32(smem);
    const int warpM = (wid >> 2) * 64;     // 0 or 64
    const int warpN = (wid & 3) * 16;      // 0,16,32,48
    const uint32_t aOff =
        (uint32_t)((warpM + (lane & 15)) * QK_STRIDE + ((lane >> 4) << 3)) * 2;
    const int bg = lane >> 3;
    const uint32_t bOff =
        (uint32_t)((warpN + ((bg >> 1) << 3) + (lane & 7)) * QK_STRIDE +
                   ((bg & 1) << 3)) * 2;

    __nv_bfloat16* sAh = (__nv_bfloat16*)(smem + QS_AHI);
    __nv_bfloat16* sAl = (__nv_bfloat16*)(smem + QS_ALO);
    float* stage = (float*)smem;

    for (int my = 0; my < 6; my++) {
        __syncthreads();   // stage/stageX reads of previous phase done
        // ---- load A (w m-block) hi/lo ----
#pragma unroll
        for (int it = 0; it < 8; it++) {
            const int idx = it * 256 + tid;
            const int row = idx >> 4, c8 = (idx & 15) << 3;
            const int so = row * QK_STRIDE + c8;
            const size_t ga = (size_t)(my * 128 + row) * C + c8;
            *(uint4*)&sAh[so] = *(const uint4*)&g_w_hi[ga];
            *(uint4*)&sAl[so] = *(const uint4*)&g_w_lo[ga];
        }
        __syncthreads();

        float acc[4][2][4] = {};
#pragma unroll
        for (int ks = 0; ks < 8; ks++) {
            const uint32_t kOff = (uint32_t)ks * 32;
            uint32_t bh[2][2], bl[2][2];
            {
                uint32_t r[4];
                ldsm4(r, sb + QS_BHI + bOff + kOff);
                bh[0][0] = r[0]; bh[0][1] = r[1]; bh[1][0] = r[2]; bh[1][1] = r[3];
                ldsm4(r, sb + QS_BLO + bOff + kOff);
                bl[0][0] = r[0]; bl[0][1] = r[1]; bl[1][0] = r[2]; bl[1][1] = r[3];
            }
#pragma unroll
            for (int mi = 0; mi < 4; mi++) {
                const uint32_t mo = (uint32_t)(mi * 16 * QK_STRIDE * 2);
                uint32_t ah[4], al[4];
                ldsm4(ah, sb + QS_AHI + aOff + mo + kOff);
                ldsm4(al, sb + QS_ALO + aOff + mo + kOff);
#pragma unroll
                for (int ni = 0; ni < 2; ni++) {
                    mma_bf16(acc[mi][ni], ah, bh[ni]);
                    mma_bf16(acc[mi][ni], ah, bl[ni]);
                    mma_bf16(acc[mi][ni], al, bh[ni]);
                }
            }
        }
        __syncthreads();   // A reads done; stage (overlapping A) safe to write

        if (my < 2) {
            // ---- q: transposed stage[n=64][c=128], stride 132 ----
#pragma unroll
            for (int mi = 0; mi < 4; mi++) {
                const int r0 = warpM + mi * 16 + (lane >> 2);
#pragma unroll
                for (int ni = 0; ni < 2; ni++) {
                    const int c0 = warpN + ni * 8 + (lane & 3) * 2;   // n index
                    stage[c0 * 132 + r0]             = acc[mi][ni][0];
                    stage[(c0 + 1) * 132 + r0]       = acc[mi][ni][1];
                    stage[c0 * 132 + r0 + 8]         = acc[mi][ni][2];
                    stage[(c0 + 1) * 132 + r0 + 8]   = acc[mi][ni][3];
                }
            }
            __syncthreads();
            {
                // softmax per (n, head-group): n = tid>>2 (0..63), hg = tid&3
                const int n = tid >> 2, hg = tid & 3;
                float* row = &stage[n * 132 + hg * DH];
                float e[DH];
                float s = 0.f;
#pragma unroll
                for (int j = 0; j < DH; j += 4) {
                    float4 v = *(const float4*)&row[j];
                    e[j] = __expf(v.x); e[j + 1] = __expf(v.y);
                    e[j + 2] = __expf(v.z); e[j + 3] = __expf(v.w);
                    s += e[j] + e[j + 1] + e[j + 2] + e[j + 3];
                }
                const float inv = QSCALE / s;
#pragma unroll
                for (int j = 0; j < DH; j += 4)
                    *(float4*)&row[j] = make_float4(
                        e[j] * inv, e[j + 1] * inv, e[j + 2] * inv, e[j + 3] * inv);
            }
            __syncthreads();
            __nv_bfloat16* ph = g_pt_hi + (size_t)bz * NSP * HID;
            __nv_bfloat16* pl = g_pt_lo + (size_t)bz * NSP * HID;
#pragma unroll
            for (int it = 0; it < 16; it++) {      // 64 n x 128 c = 4096 bf162
                const int linear = it * 256 + tid;
                const int n = linear >> 6, c = (linear & 63) * 2;
                const float p0 = stage[n * 132 + c];
                const float p1 = stage[n * 132 + c + 1];
                __nv_bfloat162 h2, l2;
                h2.x = __float2bfloat16(p0);
                h2.y = __float2bfloat16(p1);
                l2.x = __float2bfloat16(p0 - __bfloat162float(h2.x));
                l2.y = __float2bfloat16(p1 - __bfloat162float(h2.y));
                const size_t o = (size_t)(nBase + n) * HID + my * 128 + c;
                *(__nv_bfloat162*)&ph[o] = h2;
                *(__nv_bfloat162*)&pl[o] = l2;
            }
        } else {
            // ---- k / v: normal stage[m=128][n=64], stride 68 ----
#pragma unroll
            for (int mi = 0; mi < 4; mi++) {
                const int r0 = warpM + mi * 16 + (lane >> 2);
#pragma unroll
                for (int ni = 0; ni < 2; ni++) {
                    const int c0 = warpN + ni * 8 + (lane & 3) * 2;
                    stage[r0 * 68 + c0]           = acc[mi][ni][0];
                    stage[r0 * 68 + c0 + 1]       = acc[mi][ni][1];
                    stage[(r0 + 8) * 68 + c0]     = acc[mi][ni][2];
                    stage[(r0 + 8) * 68 + c0 + 1] = acc[mi][ni][3];
                }
            }
            __syncthreads();

            __nv_bfloat16 *dh, *dl;
            if (my < 4) {
                // k path: exp in place + per-row partial sums
                const int r = tid >> 1, chalf = (tid & 1) * 32;
                float s = 0.f;
#pragma unroll
                for (int c = 0; c < 32; c++) {
                    float e = __expf(stage[r * 68 + chalf + c]);
                    stage[r * 68 + chalf + c] = e;
                    s += e;
                }
                s += __shfl_xor_sync(0xFFFFFFFFu, s, 1);
                if ((tid & 1) == 0) {
                    const int kr = (my - 2) * 128 + r;
                    g_ksump[((size_t)bz * HID + kr) * NBLK + blockIdx.x] = s;
                }
                __syncthreads();
                dh = g_ek_hi + ((size_t)bz * HID + (my - 2) * 128) * NSP + nBase;
                dl = g_ek_lo + ((size_t)bz * HID + (my - 2) * 128) * NSP + nBase;
            } else {
                dh = g_v_hi + ((size_t)bz * HID + (my - 4) * 128) * NSP + nBase;
                dl = g_v_lo + ((size_t)bz * HID + (my - 4) * 128) * NSP + nBase;
            }

#pragma unroll
            for (int it = 0; it < 16; it++) {      // 128 x 64 = 4096 bf162
                const int linear = it * 256 + tid;
                const int row = linear >> 5, cp = (linear & 31) * 2;
                const float p0 = stage[row * 68 + cp];
                const float p1 = stage[row * 68 + cp + 1];
                __nv_bfloat162 h2, l2;
                h2.x = __float2bfloat16(p0);
                h2.y = __float2bfloat16(p1);
                l2.x = __float2bfloat16(p0 - __bfloat162float(h2.x));
                l2.y = __float2bfloat16(p1 - __bfloat162float(h2.y));
                *(__nv_bfloat162*)&dh[(size_t)row * NSP + cp] = h2;
                *(__nv_bfloat162*)&dl[(size_t)row * NSP + cp] = l2;
            }
        }
    }
}

// ============================================================================
// K2 (tensor core): context partials ctx[b,h,d,e] = sum_n ek[d,n] * v[e,n]
// grid (NSPLIT, HEADS, B), 256 threads (8 warps), warp = 16-wide k-slice.
// ============================================================================
#define CT_ST  136
#define CT_TB  (32 * CT_ST * 2)
#define CT_EH  0
#define CT_EL  (CT_EH + CT_TB)
#define CT_VH  (CT_EL + CT_TB)
#define CT_VL  (CT_VH + CT_TB)
#define CT_SM  (CT_VL + CT_TB)

__global__ __launch_bounds__(256) void k_ctx() {
    __shared__ char sm[CT_SM];
    const int sp = blockIdx.x, h = blockIdx.y, b = blockIdx.z;
    const int tid = threadIdx.x, wid = tid >> 5, lane = tid & 31;
    const size_t rowbase = ((size_t)b * HID + h * DH) * NSP;
    const uint32_t sb = smem_u32(sm);
    const int nb = sp * 1024;

    const uint32_t aBase =
        (uint32_t)((lane & 15) * CT_ST + ((lane >> 4) << 3) + wid * 16) * 2;
    const int bg = lane >> 3;
    const uint32_t bBase =
        (uint32_t)((((bg >> 1) << 3) + (lane & 7)) * CT_ST +
                   ((bg & 1) << 3) + wid * 16) * 2;

    float acc[2][4][4] = {};

    for (int t = 0; t < 8; t++) {
        const int n0 = nb + t * 128;
        __syncthreads();
#pragma unroll
        for (int i = 0; i < 2; i++) {
            const int idx = i * 256 + tid;
            const int row = idx >> 4, c8 = (idx & 15) << 3;
            const int so = row * CT_ST + c8;
            const size_t g = rowbase + (size_t)row * NSP + n0 + c8;
            *(uint4*)(sm + CT_EH + so * 2) = *(const uint4*)&g_ek_hi[g];
            *(uint4*)(sm + CT_EL + so * 2) = *(const uint4*)&g_ek_lo[g];
            *(uint4*)(sm + CT_VH + so * 2) = *(const uint4*)&g_v_hi[g];
            *(uint4*)(sm + CT_VL + so * 2) = *(const uint4*)&g_v_lo[g];
        }
        __syncthreads();

        uint32_t ah[2][4], al[2][4];
#pragma unroll
        for (int mt = 0; mt < 2; mt++) {
            const uint32_t mo = (uint32_t)(mt * 16 * CT_ST * 2);
            ldsm4(ah[mt], sb + CT_EH + aBase + mo);
            ldsm4(al[mt], sb + CT_EL + aBase + mo);
        }
        uint32_t bh[4][2], bl[4][2];
#pragma unroll
        for (int p = 0; p < 2; p++) {
            const uint32_t po = (uint32_t)(p * 16 * CT_ST * 2);
            uint32_t r[4];
            ldsm4(r, sb + CT_VH + bBase + po);
            bh[p * 2][0] = r[0]; bh[p * 2][1] = r[1];
            bh[p * 2 + 1][0] = r[2]; bh[p * 2 + 1][1] = r[3];
            ldsm4(r, sb + CT_VL + bBase + po);
            bl[p * 2][0] = r[0]; bl[p * 2][1] = r[1];
            bl[p * 2 + 1][0] = r[2]; bl[p * 2 + 1][1] = r[3];
        }
#pragma unroll
        for (int mt = 0; mt < 2; mt++)
#pragma unroll
            for (int ni = 0; ni < 4; ni++) {
                mma_bf16(acc[mt][ni], ah[mt], bh[ni]);
                mma_bf16(acc[mt][ni], ah[mt], bl[ni]);
                mma_bf16(acc[mt][ni], al[mt], bh[ni]);
            }
    }

    __syncthreads();
    float* red = (float*)sm;
#pragma unroll
    for (int mt = 0; mt < 2; mt++)
#pragma unroll
        for (int ni = 0; ni < 4; ni++) {
            const int r0 = mt * 16 + (lane >> 2);
            const int c0 = ni * 8 + (lane & 3) * 2;
            float* wp = red + wid * 1056;
            wp[r0 * 33 + c0]           = acc[mt][ni][0];
            wp[r0 * 33 + c0 + 1]       = acc[mt][ni][1];
            wp[(r0 + 8) * 33 + c0]     = acc[mt][ni][2];
            wp[(r0 + 8) * 33 + c0 + 1] = acc[mt][ni][3];
        }
    __syncthreads();
    float* cp = &g_ctxp[(((size_t)sp * B + b) * HEADS + h) * (DH * DH)];
    for (int idx = tid; idx < DH * DH; idx += 256) {
        const int d = idx >> 5, e = idx & 31;
        float s = 0.f;
#pragma unroll
        for (int w = 0; w < 8; w++) s += red[w * 1056 + d * 33 + e];
        cp[idx] = s;
    }
}

// ============================================================================
// K3: reduce ctx & ksum partials, normalize, fold with w_out -> bf16 hi/lo
// grid (HEADS, B), 256 threads — 32 CTAs (8x the old parallelism)
// ============================================================================
__global__ __launch_bounds__(256) void k_fold(const float* __restrict__ wout) {
    const int h = blockIdx.x, b = blockIdx.y;
    __shared__ float ctx[DH * 33];      // padded stride 33 (conflict-free fold reads)
    __shared__ float ks_s[DH];
    __shared__ float wsh[C * DH];       // w_out[:, h*32 .. h*32+32), 16 KB
    const int tid = threadIdx.x;

    // ---- ksum: 8 threads per row d, each sums 64 of the 512 partials ----
    {
        const int d = tid >> 3, seg = tid & 7;
        const float* kp = &g_ksump[((size_t)b * HID + h * DH + d) * NBLK + seg * 64];
        float s = 0.f;
#pragma unroll
        for (int i = 0; i < 64; i += 4) {
            float4 v = *(const float4*)&kp[i];
            s += v.x + v.y + v.z + v.w;
        }
#pragma unroll
        for (int off = 4; off > 0; off >>= 1)
            s += __shfl_xor_sync(0xFFFFFFFFu, s, off);
        if (seg == 0) ks_s[d] = s;
    }

    // ---- preload w_out slice [128 o][32 e] into smem (coalesced rows) ----
    for (int i = tid; i < C * DH; i += 256) {
        const int o = i >> 5, e = i & 31;
        wsh[i] = wout[o * HID + h * DH + e];
    }
    __syncthreads();

    // ---- ctx reduction over 32 sp partials (4 elems/thread, coalesced) ----
    {
        float s0 = 0.f, s1 = 0.f, s2 = 0.f, s3 = 0.f;
        const size_t base = ((size_t)b * HEADS + h) * (DH * DH);
        const size_t stride = (size_t)B * HEADS * DH * DH;
        for (int sp = 0; sp < NSPLIT; sp++) {
            const float* p = &g_ctxp[sp * stride + base];
            s0 += p[tid];
            s1 += p[tid + 256];
            s2 += p[tid + 512];
            s3 += p[tid + 768];
        }
        // normalize by ksum of row d and store padded
        const int d0 = tid >> 5, e0 = tid & 31;
        ctx[d0 * 33 + e0]        = s0 / ks_s[d0];
        ctx[(d0 + 8) * 33 + e0]  = s1 / ks_s[d0 + 8];
        ctx[(d0 + 16) * 33 + e0] = s2 / ks_s[d0 + 16];
        ctx[(d0 + 24) * 33 + e0] = s3 / ks_s[d0 + 24];
    }
    __syncthreads();

    // ---- fold: M[o][h*32+d] = sum_e w[o][e] * ctx[d][e], 4096 outputs ----
    __nv_bfloat16* mh = g_M_hi + (size_t)b * C * HID + h * DH;
    __nv_bfloat16* ml = g_M_lo + (size_t)b * C * HID + h * DH;
    for (int idx = tid; idx < C * DH; idx += 256) {
        const int o = idx >> 5, d = idx & 31;
        const float* wrow = &wsh[o * DH];
        const float* crow = &ctx[d * 33];
        float s = 0.f;
#pragma unroll
        for (int e = 0; e < DH; e++) s = fmaf(wrow[e], crow[e], s);
        __nv_bfloat16 hh = __float2bfloat16(s);
        mh[(size_t)o * HID + d] = hh;
        ml[(size_t)o * HID + d] = __float2bfloat16(s - __bfloat162float(hh));
    }
}

// ============================================================================
// K4 (tensor core): out[b][o][n] = sum_c M[o][c] * p[c][n] + bias[o]
// 128m x 64n tiles, 2 CTAs/SM; K=256 as two halves. grid (512, B)
// ============================================================================
__global__ __launch_bounds__(256, 2) void k_out_mma(float* __restrict__ out,
                                                   const float* __restrict__ bout) {
    extern __shared__ char smem[];
    const int tid = threadIdx.x, wid = tid >> 5, lane = tid & 31;
    const int bz = blockIdx.y;
    const int nBase = blockIdx.x * 64;

    const uint32_t sb = smem_u32(smem);
    const int warpM = (wid >> 2) * 64;
    const int warpN = (wid & 3) * 16;
    const uint32_t aOff =
        (uint32_t)((warpM + (lane & 15)) * QK_STRIDE + ((lane >> 4) << 3)) * 2;
    const int bg = lane >> 3;
    const uint32_t bOff =
        (uint32_t)((warpN + ((bg >> 1) << 3) + (lane & 7)) * QK_STRIDE +
                   ((bg & 1) << 3)) * 2;

    float acc[4][2][4] = {};

    for (int kh = 0; kh < 2; kh++) {
        if (kh) __syncthreads();
        {
            const __nv_bfloat16* mh = g_M_hi + (size_t)bz * C * HID + kh * 128;
            const __nv_bfloat16* ml = g_M_lo + (size_t)bz * C * HID + kh * 128;
            const __nv_bfloat16* ph = g_pt_hi + (size_t)bz * NSP * HID + kh * 128;
            const __nv_bfloat16* pl = g_pt_lo + (size_t)bz * NSP * HID + kh * 128;
            __nv_bfloat16* sAh = (__nv_bfloat16*)(smem + QS_AHI);
            __nv_bfloat16* sAl = (__nv_bfloat16*)(smem + QS_ALO);
            __nv_bfloat16* sBh = (__nv_bfloat16*)(smem + QS_BHI);
            __nv_bfloat16* sBl = (__nv_bfloat16*)(smem + QS_BLO);
#pragma unroll
            for (int it = 0; it < 8; it++) {       // A: 2048 uint4
                const int idx = it * 256 + tid;
                const int row = idx >> 4, c8 = (idx & 15) << 3;
                const int so = row * QK_STRIDE + c8;
                const size_t ga = (size_t)row * HID + c8;
                *(uint4*)&sAh[so] = *(const uint4*)&mh[ga];
                *(uint4*)&sAl[so] = *(const uint4*)&ml[ga];
            }
#pragma unroll
            for (int it = 0; it < 4; it++) {       // B: 1024 uint4
                const int idx = it * 256 + tid;
                const int row = idx >> 4, c8 = (idx & 15) << 3;
                const int so = row * QK_STRIDE + c8;
                const size_t gb = (size_t)(nBase + row) * HID + c8;
                *(uint4*)&sBh[so] = *(const uint4*)&ph[gb];
                *(uint4*)&sBl[so] = *(const uint4*)&pl[gb];
            }
        }
        __syncthreads();

#pragma unroll
        for (int ks = 0; ks < 8; ks++) {
            const uint32_t kOff = (uint32_t)ks * 32;
            uint32_t bh[2][2], bl[2][2];
            {
                uint32_t r[4];
                ldsm4(r, sb + QS_BHI + bOff + kOff);
                bh[0][0] = r[0]; bh[0][1] = r[1]; bh[1][0] = r[2]; bh[1][1] = r[3];
                ldsm4(r, sb + QS_BLO + bOff + kOff);
                bl[0][0] = r[0]; bl[0][1] = r[1]; bl[1][0] = r[2]; bl[1][1] = r[3];
            }
#pragma unroll
            for (int mi = 0; mi < 4; mi++) {
                const uint32_t mo = (uint32_t)(mi * 16 * QK_STRIDE * 2);
                uint32_t ah[4], al[4];
                ldsm4(ah, sb + QS_AHI + aOff + mo + kOff);
                ldsm4(al, sb + QS_ALO + aOff + mo + kOff);
#pragma unroll
                for (int ni = 0; ni < 2; ni++) {
                    mma_bf16(acc[mi][ni], ah, bh[ni]);
                    mma_bf16(acc[mi][ni], ah, bl[ni]);
                    mma_bf16(acc[mi][ni], al, bh[ni]);
                }
            }
        }
    }

    __syncthreads();
    float* stage = (float*)smem;           // [128][68]
#pragma unroll
    for (int mi = 0; mi < 4; mi++) {
        const int r0 = warpM + mi * 16 + (lane >> 2);
#pragma unroll
        for (int ni = 0; ni < 2; ni++) {
            const int c0 = warpN + ni * 8 + (lane & 3) * 2;
            stage[r0 * 68 + c0]           = acc[mi][ni][0];
            stage[r0 * 68 + c0 + 1]       = acc[mi][ni][1];
            stage[(r0 + 8) * 68 + c0]     = acc[mi][ni][2];
            stage[(r0 + 8) * 68 + c0 + 1] = acc[mi][ni][3];
        }
    }
    __syncthreads();
    float* Cp = out + (size_t)bz * C * NSP + nBase;
#pragma unroll
    for (int it = 0; it < 8; it++) {               // 128 x 64 = 2048 float4
        const int idx = it * 256 + tid;
        const int row = idx >> 4, c4 = (idx & 15) << 2;
        const float bb = __ldg(&bout[row]);
        float4 v = *(float4*)&stage[row * 68 + c4];
        v.x += bb; v.y += bb; v.z += bb; v.w += bb;
        *(float4*)&Cp[(size_t)row * NSP + c4] = v;
    }
}

// ============================================================================
extern "C" void kernel_launch(void* const* d_in, const int* in_sizes, int n_in,
                              void* d_out, int out_size) {
    const float* x    = (const float*)d_in[0];
    const float* wqkv = (const float*)d_in[1];
    const float* wout = (const float*)d_in[2];
    const float* bout = (const float*)d_in[3];
    float* out = (float*)d_out;

    cudaFuncSetAttribute(k_qkv_mma, cudaFuncAttributeMaxDynamicSharedMemorySize,
                         QS_TOT);
    cudaFuncSetAttribute(k_out_mma, cudaFuncAttributeMaxDynamicSharedMemorySize,
                         QS_TOT);

    k_cvt_w  <<<(M3 * C + 255) / 256, 256>>>(wqkv);
    k_qkv_mma<<<dim3(NBLK, B), 256, QS_TOT>>>(x);
    k_ctx    <<<dim3(NSPLIT, HEADS, B), 256>>>();
    k_fold   <<<dim3(HEADS, B), 256>>>(wout);
    k_out_mma<<<dim3(NSP / 64, B), 256, QS_TOT>>>(out, bout);
}